// round 1
// baseline (speedup 1.0000x reference)
#include <cuda_runtime.h>

#define N_NODES 20000
#define DDEG 16
#define F 128
#define G4 512
#define TILE_M 64
#define LDA 132   // padded row stride for A/H tiles (floats)

// -------- scratch (static device memory; no runtime allocation) --------
__device__ float g_XW[N_NODES * G4];   // precomputed input projection + bias, gate-interleaved cols
__device__ float g_WTih[F * G4];       // Wih reordered:  [k][4j+g]
__device__ float g_WThh[F * G4];       // Whh reordered:  [k][4j+g]
__device__ float g_bias[G4];           // (bih+bhh) gate-interleaved
__device__ float g_HN[N_NODES * F];    // LSTM final hidden
__device__ float g_H1[N_NODES * F];    // layer-1 output (relu)
__device__ float g_WcT[2 * F * F];     // [Wself;Wneigh] transposed: [256 k][128 cols]

__device__ __forceinline__ float sigf(float x) {
    return __fdividef(1.0f, 1.0f + __expf(-x));
}

// ---- reorder weights: interleave gates (col = 4j+g) and transpose to [k][col]
__global__ void reorder_k(const float* __restrict__ Wih, const float* __restrict__ Whh,
                          const float* __restrict__ bih, const float* __restrict__ bhh) {
    int idx = blockIdx.x * blockDim.x + threadIdx.x;
    if (idx < F * G4) {
        int k = idx / G4, col = idx % G4;
        int j = col >> 2, g = col & 3;
        int src = (g * F + j) * F + k;
        g_WTih[idx] = Wih[src];
        g_WThh[idx] = Whh[src];
    }
    if (idx < G4) {
        int j = idx >> 2, g = idx & 3;
        g_bias[idx] = bih[g * F + j] + bhh[g * F + j];
    }
}

// ---- input projection: g_XW[m, col] = bias[col] + sum_k A[m,k] * WTih[k,col]
__global__ void __launch_bounds__(256, 2) proj_k(const float* __restrict__ A, int from_h1) {
    extern __shared__ float sm[];
    float* As = sm;                     // 64 x 132
    float* Ws = sm + TILE_M * LDA;      // 128 x 64 (k-major rows)
    const float* Ap = from_h1 ? g_H1 : A;
    int m0 = blockIdx.x * TILE_M;
    int co = blockIdx.y * 64;
    int tid = threadIdx.x;

    for (int i = tid; i < TILE_M * 32; i += 256) {
        int r = i >> 5, k4 = (i & 31) * 4;
        int m = m0 + r; if (m >= N_NODES) m = N_NODES - 1;
        *(float4*)(As + r * LDA + k4) = *(const float4*)(Ap + m * F + k4);
    }
    for (int i = tid; i < F * 16; i += 256) {
        int k = i >> 4, c4 = (i & 15) * 4;
        *(float4*)(Ws + k * 64 + c4) = *(const float4*)(g_WTih + k * G4 + co + c4);
    }
    __syncthreads();

    int ty = tid >> 4, tx = tid & 15;
    float acc[4][4] = {};
    #pragma unroll 8
    for (int k4 = 0; k4 < 32; ++k4) {
        float4 a[4], w[4];
        #pragma unroll
        for (int ri = 0; ri < 4; ++ri)
            a[ri] = *(const float4*)(As + (ty * 4 + ri) * LDA + k4 * 4);
        #pragma unroll
        for (int kk = 0; kk < 4; ++kk)
            w[kk] = *(const float4*)(Ws + (k4 * 4 + kk) * 64 + tx * 4);
        #pragma unroll
        for (int kk = 0; kk < 4; ++kk) {
            float4 wv = w[kk];
            #pragma unroll
            for (int ri = 0; ri < 4; ++ri) {
                float av = ((const float*)&a[ri])[kk];
                acc[ri][0] += av * wv.x;
                acc[ri][1] += av * wv.y;
                acc[ri][2] += av * wv.z;
                acc[ri][3] += av * wv.w;
            }
        }
    }
    float4 bv = *(const float4*)(g_bias + co + tx * 4);
    #pragma unroll
    for (int ri = 0; ri < 4; ++ri) {
        int m = m0 + ty * 4 + ri;
        if (m < N_NODES) {
            float4 o;
            o.x = acc[ri][0] + bv.x; o.y = acc[ri][1] + bv.y;
            o.z = acc[ri][2] + bv.z; o.w = acc[ri][3] + bv.w;
            *(float4*)(g_XW + m * G4 + co + tx * 4) = o;
        }
    }
}

// ---- fused LSTM recurrence: 64 nodes per CTA, 16 steps, gates via tiled GEMM,
//      cell state in registers, h double-buffered in smem.
__global__ void __launch_bounds__(256, 2) lstm_k(const int* __restrict__ nbr) {
    extern __shared__ float sm[];
    float* Hs0 = sm;                         // 64*132
    float* Hs1 = sm + TILE_M * LDA;          // 64*132
    float* Ws  = sm + 2 * TILE_M * LDA;      // 128*64
    int* idx_sh = (int*)(Ws + F * 64);       // 64*16
    int m0 = blockIdx.x * TILE_M;
    int tid = threadIdx.x;

    for (int i = tid; i < TILE_M * LDA; i += 256) Hs0[i] = 0.0f;
    for (int i = tid; i < TILE_M * DDEG; i += 256) {
        int r = i >> 4, t = i & 15;
        int m = m0 + r; if (m >= N_NODES) m = N_NODES - 1;
        idx_sh[i] = nbr[m * DDEG + t];
    }

    int ty = tid >> 4, tx = tid & 15;
    float cst[8][4];
    #pragma unroll
    for (int a = 0; a < 8; ++a)
        #pragma unroll
        for (int b = 0; b < 4; ++b) cst[a][b] = 0.0f;

    float* cur = Hs0;
    float* nxt = Hs1;

    for (int t = 0; t < DDEG; ++t) {
        for (int cl = 0; cl < 8; ++cl) {
            __syncthreads();   // prior chunk's Ws reads done; also orders h writes vs next-step reads
            for (int i = tid; i < F * 16; i += 256) {
                int k = i >> 4, c4 = (i & 15) * 4;
                *(float4*)(Ws + k * 64 + c4) =
                    *(const float4*)(g_WThh + k * G4 + cl * 64 + c4);
            }
            __syncthreads();

            float acc[4][4] = {};
            #pragma unroll 8
            for (int k4 = 0; k4 < 32; ++k4) {
                float4 a[4], w[4];
                #pragma unroll
                for (int ri = 0; ri < 4; ++ri)
                    a[ri] = *(const float4*)(cur + (ty * 4 + ri) * LDA + k4 * 4);
                #pragma unroll
                for (int kk = 0; kk < 4; ++kk)
                    w[kk] = *(const float4*)(Ws + (k4 * 4 + kk) * 64 + tx * 4);
                #pragma unroll
                for (int kk = 0; kk < 4; ++kk) {
                    float4 wv = w[kk];
                    #pragma unroll
                    for (int ri = 0; ri < 4; ++ri) {
                        float av = ((const float*)&a[ri])[kk];
                        acc[ri][0] += av * wv.x;
                        acc[ri][1] += av * wv.y;
                        acc[ri][2] += av * wv.z;
                        acc[ri][3] += av * wv.w;
                    }
                }
            }
            // epilogue: cols (4j+g) for j = cl*16 + tx; thread owns all 4 gates of j
            #pragma unroll
            for (int ri = 0; ri < 4; ++ri) {
                int r = ty * 4 + ri;
                int nb = idx_sh[r * DDEG + t];
                float4 xw = *(const float4*)(g_XW + nb * G4 + cl * 64 + tx * 4);
                float ig = sigf(acc[ri][0] + xw.x);
                float fg = sigf(acc[ri][1] + xw.y);
                float gg = tanhf(acc[ri][2] + xw.z);
                float og = sigf(acc[ri][3] + xw.w);
                float c = fg * cst[cl][ri] + ig * gg;
                cst[cl][ri] = c;
                nxt[r * LDA + cl * 16 + tx] = og * tanhf(c);
            }
        }
        float* tmp = cur; cur = nxt; nxt = tmp;
    }
    __syncthreads();
    for (int i = tid; i < TILE_M * 32; i += 256) {
        int r = i >> 5, j4 = (i & 31) * 4;
        int m = m0 + r;
        if (m < N_NODES)
            *(float4*)(g_HN + m * F + j4) = *(const float4*)(cur + r * LDA + j4);
    }
}

// ---- pack [Wself;Wneigh] transposed
__global__ void combprep_k(const float* __restrict__ Wself, const float* __restrict__ Wneigh) {
    int idx = blockIdx.x * blockDim.x + threadIdx.x;
    if (idx < 2 * F * F) {
        int k = idx / F, col = idx % F;
        g_WcT[idx] = (k < F) ? Wself[col * F + k] : Wneigh[col * F + (k - F)];
    }
}

// ---- layer-1 combine: g_H1 = relu([x | HN] @ WcT + bneigh)
__global__ void __launch_bounds__(256) combine_k(const float* __restrict__ X,
                                                 const float* __restrict__ bn) {
    extern __shared__ float sm[];
    float* As = sm;                      // 64 x 260 (concat x|HN, padded)
    float* Ws = sm + TILE_M * 260;       // 256 x 64
    int m0 = blockIdx.x * TILE_M;
    int co = blockIdx.y * 64;
    int tid = threadIdx.x;

    for (int i = tid; i < TILE_M * 64; i += 256) {
        int r = i >> 6, k4 = (i & 63) * 4;
        int m = m0 + r; if (m >= N_NODES) m = N_NODES - 1;
        float4 v = (k4 < F) ? *(const float4*)(X + m * F + k4)
                            : *(const float4*)(g_HN + m * F + (k4 - F));
        *(float4*)(As + r * 260 + k4) = v;
    }
    for (int i = tid; i < 2 * F * 16; i += 256) {
        int k = i >> 4, c4 = (i & 15) * 4;
        *(float4*)(Ws + k * 64 + c4) = *(const float4*)(g_WcT + k * F + co + c4);
    }
    __syncthreads();

    int ty = tid >> 4, tx = tid & 15;
    float acc[4][4] = {};
    #pragma unroll 8
    for (int k4 = 0; k4 < 64; ++k4) {
        float4 a[4], w[4];
        #pragma unroll
        for (int ri = 0; ri < 4; ++ri)
            a[ri] = *(const float4*)(As + (ty * 4 + ri) * 260 + k4 * 4);
        #pragma unroll
        for (int kk = 0; kk < 4; ++kk)
            w[kk] = *(const float4*)(Ws + (k4 * 4 + kk) * 64 + tx * 4);
        #pragma unroll
        for (int kk = 0; kk < 4; ++kk) {
            float4 wv = w[kk];
            #pragma unroll
            for (int ri = 0; ri < 4; ++ri) {
                float av = ((const float*)&a[ri])[kk];
                acc[ri][0] += av * wv.x;
                acc[ri][1] += av * wv.y;
                acc[ri][2] += av * wv.z;
                acc[ri][3] += av * wv.w;
            }
        }
    }
    #pragma unroll
    for (int ri = 0; ri < 4; ++ri) {
        int m = m0 + ty * 4 + ri;
        if (m < N_NODES) {
            float4 o;
            float b0 = bn[co + tx * 4 + 0], b1 = bn[co + tx * 4 + 1];
            float b2 = bn[co + tx * 4 + 2], b3 = bn[co + tx * 4 + 3];
            o.x = fmaxf(acc[ri][0] + b0, 0.0f);
            o.y = fmaxf(acc[ri][1] + b1, 0.0f);
            o.z = fmaxf(acc[ri][2] + b2, 0.0f);
            o.w = fmaxf(acc[ri][3] + b3, 0.0f);
            *(float4*)(g_H1 + m * F + co + tx * 4) = o;
        }
    }
}

// ---- final: out[n] = sigmoid(H1[n].Wself2 + HN[n].Wneigh2 + b)
__global__ void final_k(const float* __restrict__ Ws2, const float* __restrict__ Wn2,
                        const float* __restrict__ bn2, float* __restrict__ out) {
    int w = (blockIdx.x * blockDim.x + threadIdx.x) >> 5;
    int lane = threadIdx.x & 31;
    if (w >= N_NODES) return;
    float s = 0.0f;
    #pragma unroll
    for (int kk = 0; kk < 4; ++kk) {
        int k = lane + kk * 32;
        s += g_H1[w * F + k] * Ws2[k] + g_HN[w * F + k] * Wn2[k];
    }
    #pragma unroll
    for (int o = 16; o > 0; o >>= 1) s += __shfl_down_sync(0xffffffffu, s, o);
    if (lane == 0) out[w] = sigf(s + bn2[0]);
}

extern "C" void kernel_launch(void* const* d_in, const int* in_sizes, int n_in,
                              void* d_out, int out_size) {
    const float* x       = (const float*)d_in[0];
    const int*   nbr     = (const int*)d_in[1];
    const float* Wih1    = (const float*)d_in[2];
    const float* Whh1    = (const float*)d_in[3];
    const float* bih1    = (const float*)d_in[4];
    const float* bhh1    = (const float*)d_in[5];
    const float* Wself1  = (const float*)d_in[6];
    const float* Wneigh1 = (const float*)d_in[7];
    const float* bneigh1 = (const float*)d_in[8];
    const float* Wih2    = (const float*)d_in[9];
    const float* Whh2    = (const float*)d_in[10];
    const float* bih2    = (const float*)d_in[11];
    const float* bhh2    = (const float*)d_in[12];
    const float* Wself2  = (const float*)d_in[13];
    const float* Wneigh2 = (const float*)d_in[14];
    const float* bneigh2 = (const float*)d_in[15];
    float* out = (float*)d_out;

    const int SM_PROJ = (TILE_M * LDA + F * 64) * 4;                 // 66560
    const int SM_LSTM = (2 * TILE_M * LDA + F * 64) * 4 + TILE_M * DDEG * 4;  // 104448
    const int SM_COMB = (TILE_M * 260 + 2 * F * 64) * 4;             // 132096

    cudaFuncSetAttribute(proj_k,    cudaFuncAttributeMaxDynamicSharedMemorySize, SM_PROJ);
    cudaFuncSetAttribute(lstm_k,    cudaFuncAttributeMaxDynamicSharedMemorySize, SM_LSTM);
    cudaFuncSetAttribute(combine_k, cudaFuncAttributeMaxDynamicSharedMemorySize, SM_COMB);

    int MT = (N_NODES + TILE_M - 1) / TILE_M;  // 313

    // ---- layer 1 ----
    reorder_k<<<(F * G4 + 255) / 256, 256>>>(Wih1, Whh1, bih1, bhh1);
    proj_k<<<dim3(MT, 8), 256, SM_PROJ>>>(x, 0);
    lstm_k<<<MT, 256, SM_LSTM>>>(nbr);
    combprep_k<<<(2 * F * F + 255) / 256, 256>>>(Wself1, Wneigh1);
    combine_k<<<dim3(MT, 2), 256, SM_COMB>>>(x, bneigh1);

    // ---- layer 2 ----
    reorder_k<<<(F * G4 + 255) / 256, 256>>>(Wih2, Whh2, bih2, bhh2);
    proj_k<<<dim3(MT, 8), 256, SM_PROJ>>>(nullptr, 1);
    lstm_k<<<MT, 256, SM_LSTM>>>(nbr);
    final_k<<<(N_NODES * 32 + 255) / 256, 256>>>(Wself2, Wneigh2, bneigh2, out);
}

// round 5
// speedup vs baseline: 3.1592x; 3.1592x over previous
#include <cuda_runtime.h>

#define N_NODES 20000
#define DDEG 16
#define F 128
#define G4 512

// -------- scratch (static device memory) --------
__device__ float  g_XW[N_NODES * G4];      // input projection + bias, packed gate cols
__device__ float  g_bias[G4];              // (bih+bhh), packed cols
__device__ float2 g_BpackIH[16 * 64 * 32]; // Wih in mma B-fragment order
__device__ float2 g_BpackHH[16 * 64 * 32]; // Whh in mma B-fragment order
__device__ float  g_HN[N_NODES * F];       // LSTM final hidden
__device__ float  g_H1[N_NODES * F];       // layer-1 output (relu)
__device__ float  g_WcT[2 * F * F];        // [Wself;Wneigh]^T

__device__ __forceinline__ float sigf(float x) {
    return __fdividef(1.0f, 1.0f + __expf(-x));
}
__device__ __forceinline__ float tanhf2(float x) {
    return 1.0f - __fdividef(2.0f, __expf(2.0f * x) + 1.0f);
}
__device__ __forceinline__ float to_tf32(float x) {
    unsigned u;
    asm("cvt.rna.tf32.f32 %0, %1;" : "=r"(u) : "f"(x));
    return __uint_as_float(u);
}
__device__ __forceinline__ void mma_tf32(float* d, unsigned a0, unsigned a1,
                                         unsigned a2, unsigned a3,
                                         unsigned b0, unsigned b1) {
    asm volatile(
        "mma.sync.aligned.m16n8k8.row.col.f32.tf32.tf32.f32 "
        "{%0,%1,%2,%3}, {%4,%5,%6,%7}, {%8,%9}, {%0,%1,%2,%3};\n"
        : "+f"(d[0]), "+f"(d[1]), "+f"(d[2]), "+f"(d[3])
        : "r"(a0), "r"(a1), "r"(a2), "r"(a3), "r"(b0), "r"(b1));
}

// Packed gate-column mapping: col c <-> (hidden j, gate g):
//   j = 4*(c>>4) + ((c&7)>>1),  g = (c&1) + 2*((c>>3)&1)   (gate order i,f,g,o)
// Thread (lane) with tig=lane&3 then owns, in D-fragment regs of n8-tile pair
// (2g16, 2g16+1): (i,f) and (g,o) of unit j = 16w + 4*g16 + tig.

// ---- one-time weight packing: B fragments + packed bias
__global__ void reorder2_k(const float* __restrict__ Wih, const float* __restrict__ Whh,
                           const float* __restrict__ bih, const float* __restrict__ bhh) {
    int idx = blockIdx.x * blockDim.x + threadIdx.x;
    if (idx < 16 * 64 * 32) {
        int l = idx & 31, t = (idx >> 5) & 63, s = idx >> 11;
        int tig = l & 3, gid = l >> 2;
        int c = 8 * t + gid;
        int j = 4 * (c >> 4) + ((c & 7) >> 1);
        int g = (c & 1) + 2 * ((c >> 3) & 1);
        int row = g * F + j;
        int k0 = 8 * s + tig;
        float2 bh, bi;
        bh.x = to_tf32(Whh[row * F + k0]);
        bh.y = to_tf32(Whh[row * F + k0 + 4]);
        bi.x = to_tf32(Wih[row * F + k0]);
        bi.y = to_tf32(Wih[row * F + k0 + 4]);
        g_BpackHH[idx] = bh;
        g_BpackIH[idx] = bi;
    }
    if (idx < G4) {
        int c = idx;
        int j = 4 * (c >> 4) + ((c & 7) >> 1);
        int g = (c & 1) + 2 * ((c >> 3) & 1);
        g_bias[c] = bih[g * F + j] + bhh[g * F + j];
    }
}

// ---- tensor-core input projection: g_XW[m, c] = (A @ Wih^T)[m,c] + bias[c]
__global__ void __launch_bounds__(256, 1) proj2_k(const float* __restrict__ X, int from_h1) {
    __shared__ float a_sh[64 * 132];
    int tid = threadIdx.x, w = tid >> 5, lane = tid & 31;
    int gid = lane >> 2, tig = lane & 3;
    int m0 = blockIdx.x * 64;
    const float* Ap = from_h1 ? g_H1 : X;

    for (int i = tid; i < 64 * 32; i += 256) {
        int r = i >> 5, k4 = (i & 31) * 4;
        int m = m0 + r; if (m >= N_NODES) m = N_NODES - 1;
        *(float4*)(a_sh + r * 132 + k4) = *(const float4*)(Ap + m * F + k4);
    }
    __syncthreads();

    float acc[4][8][4];
    #pragma unroll
    for (int a = 0; a < 4; ++a)
        #pragma unroll
        for (int b = 0; b < 8; ++b)
            #pragma unroll
            for (int cc = 0; cc < 4; ++cc) acc[a][b][cc] = 0.0f;

    float2 bv[2][8];
    #pragma unroll
    for (int nt = 0; nt < 8; ++nt) bv[0][nt] = g_BpackIH[(w * 8 + nt) * 32 + lane];

    #pragma unroll
    for (int s = 0; s < 16; ++s) {
        int cur = s & 1;
        if (s < 15) {
            #pragma unroll
            for (int nt = 0; nt < 8; ++nt)
                bv[cur ^ 1][nt] = g_BpackIH[((s + 1) * 64 + w * 8 + nt) * 32 + lane];
        }
        #pragma unroll
        for (int mt = 0; mt < 4; ++mt) {
            const float* hr = a_sh + (mt * 16 + gid) * 132 + s * 8 + tig;
            unsigned a0 = __float_as_uint(hr[0]);
            unsigned a1 = __float_as_uint(hr[8 * 132]);
            unsigned a2 = __float_as_uint(hr[4]);
            unsigned a3 = __float_as_uint(hr[8 * 132 + 4]);
            #pragma unroll
            for (int nt = 0; nt < 8; ++nt)
                mma_tf32(acc[mt][nt], a0, a1, a2, a3,
                         __float_as_uint(bv[cur][nt].x), __float_as_uint(bv[cur][nt].y));
        }
    }

    #pragma unroll
    for (int nt = 0; nt < 8; ++nt) {
        int col = w * 64 + nt * 8 + 2 * tig;
        float2 b2 = *(const float2*)(g_bias + col);
        #pragma unroll
        for (int mt = 0; mt < 4; ++mt) {
            #pragma unroll
            for (int rr = 0; rr < 2; ++rr) {
                int m = m0 + mt * 16 + gid + rr * 8;
                if (m < N_NODES) {
                    float2 o;
                    o.x = acc[mt][nt][rr * 2 + 0] + b2.x;
                    o.y = acc[mt][nt][rr * 2 + 1] + b2.y;
                    *(float2*)(g_XW + m * G4 + col) = o;
                }
            }
        }
    }
}

// ---- tensor-core LSTM recurrence: 64 nodes/CTA, 16 steps.
// Gates land in mma accumulators; cell state in registers; h via smem.
__global__ void __launch_bounds__(256, 1) lstm2_k(const int* __restrict__ nbr) {
    __shared__ float h_sh[64 * 132];
    __shared__ int idx_sh[64 * DDEG];
    int tid = threadIdx.x, w = tid >> 5, lane = tid & 31;
    int gid = lane >> 2, tig = lane & 3;
    int m0 = blockIdx.x * 64;

    for (int i = tid; i < 64 * 132; i += 256) h_sh[i] = 0.0f;
    for (int i = tid; i < 64 * DDEG; i += 256) {
        int r = i >> 4;
        int m = m0 + r; if (m >= N_NODES) m = N_NODES - 1;
        idx_sh[i] = nbr[m * DDEG + (i & 15)];
    }

    float cst[4][2][4];
    #pragma unroll
    for (int a = 0; a < 4; ++a)
        #pragma unroll
        for (int b = 0; b < 2; ++b)
            #pragma unroll
            for (int cc = 0; cc < 4; ++cc) cst[a][b][cc] = 0.0f;

    __syncthreads();

    for (int t = 0; t < DDEG; ++t) {
        float acc[4][8][4];
        #pragma unroll
        for (int a = 0; a < 4; ++a)
            #pragma unroll
            for (int b = 0; b < 8; ++b)
                #pragma unroll
                for (int cc = 0; cc < 4; ++cc) acc[a][b][cc] = 0.0f;

        float2 bv[2][8];
        #pragma unroll
        for (int nt = 0; nt < 8; ++nt) bv[0][nt] = g_BpackHH[(w * 8 + nt) * 32 + lane];

        #pragma unroll
        for (int s = 0; s < 16; ++s) {
            int cur = s & 1;
            if (s < 15) {
                #pragma unroll
                for (int nt = 0; nt < 8; ++nt)
                    bv[cur ^ 1][nt] = g_BpackHH[((s + 1) * 64 + w * 8 + nt) * 32 + lane];
            }
            #pragma unroll
            for (int mt = 0; mt < 4; ++mt) {
                const float* hr = h_sh + (mt * 16 + gid) * 132 + s * 8 + tig;
                unsigned a0 = __float_as_uint(hr[0]);
                unsigned a1 = __float_as_uint(hr[8 * 132]);
                unsigned a2 = __float_as_uint(hr[4]);
                unsigned a3 = __float_as_uint(hr[8 * 132 + 4]);
                #pragma unroll
                for (int nt = 0; nt < 8; ++nt)
                    mma_tf32(acc[mt][nt], a0, a1, a2, a3,
                             __float_as_uint(bv[cur][nt].x), __float_as_uint(bv[cur][nt].y));
            }
        }

        __syncthreads();   // all warps done reading h_sh(t)

        #pragma unroll
        for (int mt = 0; mt < 4; ++mt) {
            #pragma unroll
            for (int rr = 0; rr < 2; ++rr) {
                int r = mt * 16 + gid + rr * 8;
                int nb = idx_sh[r * DDEG + t];
                const float* xwb = g_XW + nb * G4 + w * 64 + 2 * tig;
                #pragma unroll
                for (int g16 = 0; g16 < 4; ++g16) {
                    float2 xif = *(const float2*)(xwb + g16 * 16);
                    float2 xgo = *(const float2*)(xwb + g16 * 16 + 8);
                    float iv = acc[mt][2 * g16][rr * 2 + 0] + xif.x;
                    float fv = acc[mt][2 * g16][rr * 2 + 1] + xif.y;
                    float gv = acc[mt][2 * g16 + 1][rr * 2 + 0] + xgo.x;
                    float ov = acc[mt][2 * g16 + 1][rr * 2 + 1] + xgo.y;
                    float cn = sigf(fv) * cst[mt][rr][g16] + sigf(iv) * tanhf2(gv);
                    cst[mt][rr][g16] = cn;
                    h_sh[r * 132 + w * 16 + 4 * g16 + tig] = sigf(ov) * tanhf2(cn);
                }
            }
        }
        __syncthreads();   // h(t+1) visible before next step's reads
    }

    for (int i = tid; i < 64 * 32; i += 256) {
        int r = i >> 5, j4 = (i & 31) * 4;
        int m = m0 + r;
        if (m < N_NODES)
            *(float4*)(g_HN + m * F + j4) = *(const float4*)(h_sh + r * 132 + j4);
    }
}

// ---- pack [Wself;Wneigh] transposed
__global__ void combprep_k(const float* __restrict__ Wself, const float* __restrict__ Wneigh) {
    int idx = blockIdx.x * blockDim.x + threadIdx.x;
    if (idx < 2 * F * F) {
        int k = idx / F, col = idx % F;
        g_WcT[idx] = (k < F) ? Wself[col * F + k] : Wneigh[col * F + (k - F)];
    }
}

// ---- layer-1 combine: g_H1 = relu([x | HN] @ WcT + bneigh)
__global__ void __launch_bounds__(256) combine_k(const float* __restrict__ X,
                                                 const float* __restrict__ bn) {
    extern __shared__ float sm[];
    float* As = sm;                      // 64 x 260
    float* Ws = sm + 64 * 260;           // 256 x 64
    int m0 = blockIdx.x * 64;
    int co = blockIdx.y * 64;
    int tid = threadIdx.x;

    for (int i = tid; i < 64 * 64; i += 256) {
        int r = i >> 6, k4 = (i & 63) * 4;
        int m = m0 + r; if (m >= N_NODES) m = N_NODES - 1;
        float4 v = (k4 < F) ? *(const float4*)(X + m * F + k4)
                            : *(const float4*)(g_HN + m * F + (k4 - F));
        *(float4*)(As + r * 260 + k4) = v;
    }
    for (int i = tid; i < 2 * F * 16; i += 256) {
        int k = i >> 4, c4 = (i & 15) * 4;
        *(float4*)(Ws + k * 64 + c4) = *(const float4*)(g_WcT + k * F + co + c4);
    }
    __syncthreads();

    int ty = tid >> 4, tx = tid & 15;
    float acc[4][4] = {};
    #pragma unroll 8
    for (int k4 = 0; k4 < 64; ++k4) {
        float4 a[4], wv4[4];
        #pragma unroll
        for (int ri = 0; ri < 4; ++ri)
            a[ri] = *(const float4*)(As + (ty * 4 + ri) * 260 + k4 * 4);
        #pragma unroll
        for (int kk = 0; kk < 4; ++kk)
            wv4[kk] = *(const float4*)(Ws + (k4 * 4 + kk) * 64 + tx * 4);
        #pragma unroll
        for (int kk = 0; kk < 4; ++kk) {
            float4 wv = wv4[kk];
            #pragma unroll
            for (int ri = 0; ri < 4; ++ri) {
                float av = ((const float*)&a[ri])[kk];
                acc[ri][0] += av * wv.x;
                acc[ri][1] += av * wv.y;
                acc[ri][2] += av * wv.z;
                acc[ri][3] += av * wv.w;
            }
        }
    }
    #pragma unroll
    for (int ri = 0; ri < 4; ++ri) {
        int m = m0 + ty * 4 + ri;
        if (m < N_NODES) {
            float4 o;
            o.x = fmaxf(acc[ri][0] + bn[co + tx * 4 + 0], 0.0f);
            o.y = fmaxf(acc[ri][1] + bn[co + tx * 4 + 1], 0.0f);
            o.z = fmaxf(acc[ri][2] + bn[co + tx * 4 + 2], 0.0f);
            o.w = fmaxf(acc[ri][3] + bn[co + tx * 4 + 3], 0.0f);
            *(float4*)(g_H1 + m * F + co + tx * 4) = o;
        }
    }
}

// ---- final: out[n] = sigmoid(H1[n].Wself2 + HN[n].Wneigh2 + b)
__global__ void final_k(const float* __restrict__ Ws2, const float* __restrict__ Wn2,
                        const float* __restrict__ bn2, float* __restrict__ out) {
    int w = (blockIdx.x * blockDim.x + threadIdx.x) >> 5;
    int lane = threadIdx.x & 31;
    if (w >= N_NODES) return;
    float s = 0.0f;
    #pragma unroll
    for (int kk = 0; kk < 4; ++kk) {
        int k = lane + kk * 32;
        s += g_H1[w * F + k] * Ws2[k] + g_HN[w * F + k] * Wn2[k];
    }
    #pragma unroll
    for (int o = 16; o > 0; o >>= 1) s += __shfl_down_sync(0xffffffffu, s, o);
    if (lane == 0) out[w] = sigf(s + bn2[0]);
}

extern "C" void kernel_launch(void* const* d_in, const int* in_sizes, int n_in,
                              void* d_out, int out_size) {
    const float* x       = (const float*)d_in[0];
    const int*   nbr     = (const int*)d_in[1];
    const float* Wih1    = (const float*)d_in[2];
    const float* Whh1    = (const float*)d_in[3];
    const float* bih1    = (const float*)d_in[4];
    const float* bhh1    = (const float*)d_in[5];
    const float* Wself1  = (const float*)d_in[6];
    const float* Wneigh1 = (const float*)d_in[7];
    const float* bneigh1 = (const float*)d_in[8];
    const float* Wih2    = (const float*)d_in[9];
    const float* Whh2    = (const float*)d_in[10];
    const float* bih2    = (const float*)d_in[11];
    const float* bhh2    = (const float*)d_in[12];
    const float* Wself2  = (const float*)d_in[13];
    const float* Wneigh2 = (const float*)d_in[14];
    const float* bneigh2 = (const float*)d_in[15];
    float* out = (float*)d_out;

    const int SM_COMB = (64 * 260 + 2 * F * 64) * 4;
    cudaFuncSetAttribute(combine_k, cudaFuncAttributeMaxDynamicSharedMemorySize, SM_COMB);

    int MT = (N_NODES + 63) / 64;   // 313

    // ---- layer 1 ----
    reorder2_k<<<128, 256>>>(Wih1, Whh1, bih1, bhh1);
    proj2_k<<<MT, 256>>>(x, 0);
    lstm2_k<<<MT, 256>>>(nbr);
    combprep_k<<<(2 * F * F + 255) / 256, 256>>>(Wself1, Wneigh1);
    combine_k<<<dim3(MT, 2), 256, SM_COMB>>>(x, bneigh1);

    // ---- layer 2 ----
    reorder2_k<<<128, 256>>>(Wih2, Whh2, bih2, bhh2);
    proj2_k<<<MT, 256>>>(nullptr, 1);
    lstm2_k<<<MT, 256>>>(nbr);
    final_k<<<(N_NODES * 32 + 255) / 256, 256>>>(Wself2, Wneigh2, bneigh2, out);
}

// round 7
// speedup vs baseline: 4.3579x; 1.3794x over previous
#include <cuda_runtime.h>
#include <cuda_fp16.h>

#define N_NODES 20000
#define DDEG 16
#define F 128
#define G4 512
#define LDH 136   // half-element row stride for fp16 A/H tiles (272B: conflict-free ldmatrix)

// -------- scratch (static device memory) --------
__device__ float g_XW[N_NODES * G4];      // input projection + bias (fp32), packed gate cols
__device__ float g_bias[G4];              // (bih+bhh), packed cols
__device__ uint2 g_BpIH[8 * 64 * 32];     // Wih fp16 B-fragments: [slice][tile][lane] = {b0,b1}
__device__ uint2 g_BpHH[8 * 64 * 32];     // Whh fp16 B-fragments
__device__ float g_HN[N_NODES * F];       // LSTM final hidden
__device__ float g_H1[N_NODES * F];       // layer-1 output (relu)
__device__ float g_WcT[2 * F * F];        // [Wself;Wneigh]^T

__device__ __forceinline__ float sigf(float x) {
    return __fdividef(1.0f, 1.0f + __expf(-x));
}
__device__ __forceinline__ float tanhf2(float x) {
    return 1.0f - __fdividef(2.0f, __expf(2.0f * x) + 1.0f);
}
__device__ __forceinline__ void ldmA(unsigned* a, const __half* p) {
    unsigned addr = (unsigned)__cvta_generic_to_shared(p);
    asm volatile("ldmatrix.sync.aligned.m8n8.x4.shared.b16 {%0,%1,%2,%3}, [%4];"
                 : "=r"(a[0]), "=r"(a[1]), "=r"(a[2]), "=r"(a[3]) : "r"(addr));
}
__device__ __forceinline__ void mma16(float* d, const unsigned* a, unsigned b0, unsigned b1) {
    asm volatile(
        "mma.sync.aligned.m16n8k16.row.col.f32.f16.f16.f32 "
        "{%0,%1,%2,%3}, {%4,%5,%6,%7}, {%8,%9}, {%0,%1,%2,%3};\n"
        : "+f"(d[0]), "+f"(d[1]), "+f"(d[2]), "+f"(d[3])
        : "r"(a[0]), "r"(a[1]), "r"(a[2]), "r"(a[3]), "r"(b0), "r"(b1));
}

// Packed gate-column mapping: col c <-> (hidden j, gate g):
//   j = 4*(c>>4) + ((c&7)>>1),  g = (c&1) + 2*((c>>3)&1)   (gate order i,f,g,o)

// ---- one-time weight packing: fp16 B fragments (m16n8k16) + packed bias
__global__ void reorder3_k(const float* __restrict__ Wih, const float* __restrict__ Whh,
                           const float* __restrict__ bih, const float* __restrict__ bhh) {
    int idx = blockIdx.x * blockDim.x + threadIdx.x;
    if (idx < 8 * 64 * 32) {
        int l = idx & 31, t = (idx >> 5) & 63, s = idx >> 11;
        int tig = l & 3, gid = l >> 2;
        int c = 8 * t + gid;
        int j = 4 * (c >> 4) + ((c & 7) >> 1);
        int g = (c & 1) + 2 * ((c >> 3) & 1);
        int row = g * F + j;
        int k0 = s * 16 + tig * 2;
        const float* wh = Whh + row * F + k0;
        const float* wi = Wih + row * F + k0;
        __half2 h0 = __floats2half2_rn(wh[0], wh[1]);
        __half2 h1 = __floats2half2_rn(wh[8], wh[9]);
        __half2 i0 = __floats2half2_rn(wi[0], wi[1]);
        __half2 i1 = __floats2half2_rn(wi[8], wi[9]);
        uint2 ph, pi;
        ph.x = *(unsigned*)&h0; ph.y = *(unsigned*)&h1;
        pi.x = *(unsigned*)&i0; pi.y = *(unsigned*)&i1;
        g_BpHH[idx] = ph;
        g_BpIH[idx] = pi;
    }
    if (idx < G4) {
        int c = idx;
        int j = 4 * (c >> 4) + ((c & 7) >> 1);
        int g = (c & 1) + 2 * ((c >> 3) & 1);
        g_bias[c] = bih[g * F + j] + bhh[g * F + j];
    }
}

// ---- tensor-core input projection: g_XW[m, c] = (A @ Wih^T)[m,c] + bias[c]
__global__ void __launch_bounds__(256, 1) proj3_k(const float* __restrict__ X, int from_h1) {
    __shared__ __half a_sh[64 * LDH];
    int tid = threadIdx.x, w = tid >> 5, lane = tid & 31;
    int gid = lane >> 2, tig = lane & 3;
    int m0 = blockIdx.x * 64;
    const float* Ap = from_h1 ? g_H1 : X;

    for (int i = tid; i < 64 * 16; i += 256) {
        int r = i >> 4, k8 = (i & 15) * 8;
        int m = m0 + r; if (m >= N_NODES) m = N_NODES - 1;
        float4 v0 = *(const float4*)(Ap + m * F + k8);
        float4 v1 = *(const float4*)(Ap + m * F + k8 + 4);
        __half2 p[4];
        p[0] = __floats2half2_rn(v0.x, v0.y);
        p[1] = __floats2half2_rn(v0.z, v0.w);
        p[2] = __floats2half2_rn(v1.x, v1.y);
        p[3] = __floats2half2_rn(v1.z, v1.w);
        *(uint4*)(a_sh + r * LDH + k8) = *(uint4*)p;
    }
    __syncthreads();

    float acc[4][8][4];
    #pragma unroll
    for (int a = 0; a < 4; ++a)
        #pragma unroll
        for (int b = 0; b < 8; ++b)
            #pragma unroll
            for (int cc = 0; cc < 4; ++cc) acc[a][b][cc] = 0.0f;

    uint2 bv[2][8];
    #pragma unroll
    for (int nt = 0; nt < 8; ++nt) bv[0][nt] = g_BpIH[(w * 8 + nt) * 32 + lane];

    int arow = lane & 15, acb = (lane >> 4) * 8;
    #pragma unroll
    for (int s = 0; s < 8; ++s) {
        int cur = s & 1;
        if (s < 7) {
            #pragma unroll
            for (int nt = 0; nt < 8; ++nt)
                bv[cur ^ 1][nt] = g_BpIH[((s + 1) * 64 + w * 8 + nt) * 32 + lane];
        }
        #pragma unroll
        for (int mt = 0; mt < 4; ++mt) {
            unsigned a[4];
            ldmA(a, a_sh + (mt * 16 + arow) * LDH + s * 16 + acb);
            #pragma unroll
            for (int nt = 0; nt < 8; ++nt)
                mma16(acc[mt][nt], a, bv[cur][nt].x, bv[cur][nt].y);
        }
    }

    #pragma unroll
    for (int nt = 0; nt < 8; ++nt) {
        int col = w * 64 + nt * 8 + 2 * tig;
        float2 b2 = *(const float2*)(g_bias + col);
        #pragma unroll
        for (int mt = 0; mt < 4; ++mt) {
            #pragma unroll
            for (int rr = 0; rr < 2; ++rr) {
                int m = m0 + mt * 16 + gid + rr * 8;
                if (m < N_NODES) {
                    float2 o;
                    o.x = acc[mt][nt][rr * 2 + 0] + b2.x;
                    o.y = acc[mt][nt][rr * 2 + 1] + b2.y;
                    *(float2*)(g_XW + m * G4 + col) = o;
                }
            }
        }
    }
}

// ---- fp16 tensor-core LSTM recurrence: 64 nodes/CTA, 16 steps, double-buffered h,
//      one barrier per step, cell state in registers, fp32 XW added in epilogue.
__global__ void __launch_bounds__(256, 1) lstm3_k(const int* __restrict__ nbr) {
    __shared__ __half h_buf[2][64 * LDH];
    __shared__ int idx_sh[64 * DDEG];
    int tid = threadIdx.x, w = tid >> 5, lane = tid & 31;
    int gid = lane >> 2, tig = lane & 3;
    int m0 = blockIdx.x * 64;

    for (int i = tid; i < 64 * LDH / 2; i += 256)
        ((__half2*)h_buf[0])[i] = __floats2half2_rn(0.f, 0.f);
    for (int i = tid; i < 64 * DDEG; i += 256) {
        int r = i >> 4;
        int m = m0 + r; if (m >= N_NODES) m = N_NODES - 1;
        idx_sh[i] = nbr[m * DDEG + (i & 15)];
    }

    float cst[4][2][4];
    #pragma unroll
    for (int a = 0; a < 4; ++a)
        #pragma unroll
        for (int b = 0; b < 2; ++b)
            #pragma unroll
            for (int cc = 0; cc < 4; ++cc) cst[a][b][cc] = 0.0f;

    __syncthreads();

    int arow = lane & 15, acb = (lane >> 4) * 8;
    int cur_buf = 0;

    for (int t = 0; t < DDEG; ++t) {
        const __half* cur = h_buf[cur_buf];
        __half* nxt = h_buf[cur_buf ^ 1];

        float acc[4][8][4];
        #pragma unroll
        for (int a = 0; a < 4; ++a)
            #pragma unroll
            for (int b = 0; b < 8; ++b)
                #pragma unroll
                for (int cc = 0; cc < 4; ++cc) acc[a][b][cc] = 0.0f;

        uint2 bv[2][8];
        #pragma unroll
        for (int nt = 0; nt < 8; ++nt) bv[0][nt] = g_BpHH[(w * 8 + nt) * 32 + lane];

        #pragma unroll
        for (int s = 0; s < 8; ++s) {
            int c2 = s & 1;
            if (s < 7) {
                #pragma unroll
                for (int nt = 0; nt < 8; ++nt)
                    bv[c2 ^ 1][nt] = g_BpHH[((s + 1) * 64 + w * 8 + nt) * 32 + lane];
            }
            #pragma unroll
            for (int mt = 0; mt < 4; ++mt) {
                unsigned a[4];
                ldmA(a, cur + (mt * 16 + arow) * LDH + s * 16 + acb);
                #pragma unroll
                for (int nt = 0; nt < 8; ++nt)
                    mma16(acc[mt][nt], a, bv[c2][nt].x, bv[c2][nt].y);
            }
        }

        // epilogue: thread owns gates (i,f)/(g,o) of unit j = 16w + 4*g16 + tig
        #pragma unroll
        for (int mt = 0; mt < 4; ++mt) {
            #pragma unroll
            for (int rr = 0; rr < 2; ++rr) {
                int r = mt * 16 + gid + rr * 8;
                int nb = idx_sh[r * DDEG + t];
                const float* xwb = g_XW + nb * G4 + w * 64 + 2 * tig;
                #pragma unroll
                for (int g16 = 0; g16 < 4; ++g16) {
                    float2 xif = *(const float2*)(xwb + g16 * 16);
                    float2 xgo = *(const float2*)(xwb + g16 * 16 + 8);
                    float iv = acc[mt][2 * g16][rr * 2 + 0] + xif.x;
                    float fv = acc[mt][2 * g16][rr * 2 + 1] + xif.y;
                    float gv = acc[mt][2 * g16 + 1][rr * 2 + 0] + xgo.x;
                    float ov = acc[mt][2 * g16 + 1][rr * 2 + 1] + xgo.y;
                    float cn = sigf(fv) * cst[mt][rr][g16] + sigf(iv) * tanhf2(gv);
                    cst[mt][rr][g16] = cn;
                    nxt[r * LDH + w * 16 + 4 * g16 + tig] = __float2half_rn(sigf(ov) * tanhf2(cn));
                }
            }
        }
        cur_buf ^= 1;
        __syncthreads();   // writes(t)->reads(t+1), and reads(t) done before writes(t+1)
    }

    const __half* hf = h_buf[cur_buf];
    for (int i = tid; i < 64 * 16; i += 256) {
        int r = i >> 4, k8 = (i & 15) * 8;
        int m = m0 + r;
        if (m < N_NODES) {
            const __half2* src = (const __half2*)(hf + r * LDH + k8);
            float4 o0, o1;
            float2 t0 = __half22float2(src[0]), t1 = __half22float2(src[1]);
            float2 t2 = __half22float2(src[2]), t3 = __half22float2(src[3]);
            o0.x = t0.x; o0.y = t0.y; o0.z = t1.x; o0.w = t1.y;
            o1.x = t2.x; o1.y = t2.y; o1.z = t3.x; o1.w = t3.y;
            *(float4*)(g_HN + m * F + k8) = o0;
            *(float4*)(g_HN + m * F + k8 + 4) = o1;
        }
    }
}

// ---- pack [Wself;Wneigh] transposed
__global__ void combprep_k(const float* __restrict__ Wself, const float* __restrict__ Wneigh) {
    int idx = blockIdx.x * blockDim.x + threadIdx.x;
    if (idx < 2 * F * F) {
        int k = idx / F, col = idx % F;
        g_WcT[idx] = (k < F) ? Wself[col * F + k] : Wneigh[col * F + (k - F)];
    }
}

// ---- layer-1 combine: g_H1 = relu([x | HN] @ WcT + bneigh)
__global__ void __launch_bounds__(256) combine_k(const float* __restrict__ X,
                                                 const float* __restrict__ bn) {
    extern __shared__ float sm[];
    float* As = sm;                      // 64 x 260
    float* Ws = sm + 64 * 260;           // 256 x 64
    int m0 = blockIdx.x * 64;
    int co = blockIdx.y * 64;
    int tid = threadIdx.x;

    for (int i = tid; i < 64 * 64; i += 256) {
        int r = i >> 6, k4 = (i & 63) * 4;
        int m = m0 + r; if (m >= N_NODES) m = N_NODES - 1;
        float4 v = (k4 < F) ? *(const float4*)(X + m * F + k4)
                            : *(const float4*)(g_HN + m * F + (k4 - F));
        *(float4*)(As + r * 260 + k4) = v;
    }
    for (int i = tid; i < 2 * F * 16; i += 256) {
        int k = i >> 4, c4 = (i & 15) * 4;
        *(float4*)(Ws + k * 64 + c4) = *(const float4*)(g_WcT + k * F + co + c4);
    }
    __syncthreads();

    int ty = tid >> 4, tx = tid & 15;
    float acc[4][4] = {};
    #pragma unroll 8
    for (int k4 = 0; k4 < 64; ++k4) {
        float4 a[4], wv4[4];
        #pragma unroll
        for (int ri = 0; ri < 4; ++ri)
            a[ri] = *(const float4*)(As + (ty * 4 + ri) * 260 + k4 * 4);
        #pragma unroll
        for (int kk = 0; kk < 4; ++kk)
            wv4[kk] = *(const float4*)(Ws + (k4 * 4 + kk) * 64 + tx * 4);
        #pragma unroll
        for (int kk = 0; kk < 4; ++kk) {
            float4 wv = wv4[kk];
            #pragma unroll
            for (int ri = 0; ri < 4; ++ri) {
                float av = ((const float*)&a[ri])[kk];
                acc[ri][0] += av * wv.x;
                acc[ri][1] += av * wv.y;
                acc[ri][2] += av * wv.z;
                acc[ri][3] += av * wv.w;
            }
        }
    }
    #pragma unroll
    for (int ri = 0; ri < 4; ++ri) {
        int m = m0 + ty * 4 + ri;
        if (m < N_NODES) {
            float4 o;
            o.x = fmaxf(acc[ri][0] + bn[co + tx * 4 + 0], 0.0f);
            o.y = fmaxf(acc[ri][1] + bn[co + tx * 4 + 1], 0.0f);
            o.z = fmaxf(acc[ri][2] + bn[co + tx * 4 + 2], 0.0f);
            o.w = fmaxf(acc[ri][3] + bn[co + tx * 4 + 3], 0.0f);
            *(float4*)(g_H1 + m * F + co + tx * 4) = o;
        }
    }
}

// ---- final: out[n] = sigmoid(H1[n].Wself2 + HN[n].Wneigh2 + b)
__global__ void final_k(const float* __restrict__ Ws2, const float* __restrict__ Wn2,
                        const float* __restrict__ bn2, float* __restrict__ out) {
    int w = (blockIdx.x * blockDim.x + threadIdx.x) >> 5;
    int lane = threadIdx.x & 31;
    if (w >= N_NODES) return;
    float s = 0.0f;
    #pragma unroll
    for (int kk = 0; kk < 4; ++kk) {
        int k = lane + kk * 32;
        s += g_H1[w * F + k] * Ws2[k] + g_HN[w * F + k] * Wn2[k];
    }
    #pragma unroll
    for (int o = 16; o > 0; o >>= 1) s += __shfl_down_sync(0xffffffffu, s, o);
    if (lane == 0) out[w] = sigf(s + bn2[0]);
}

extern "C" void kernel_launch(void* const* d_in, const int* in_sizes, int n_in,
                              void* d_out, int out_size) {
    const float* x       = (const float*)d_in[0];
    const int*   nbr     = (const int*)d_in[1];
    const float* Wih1    = (const float*)d_in[2];
    const float* Whh1    = (const float*)d_in[3];
    const float* bih1    = (const float*)d_in[4];
    const float* bhh1    = (const float*)d_in[5];
    const float* Wself1  = (const float*)d_in[6];
    const float* Wneigh1 = (const float*)d_in[7];
    const float* bneigh1 = (const float*)d_in[8];
    const float* Wih2    = (const float*)d_in[9];
    const float* Whh2    = (const float*)d_in[10];
    const float* bih2    = (const float*)d_in[11];
    const float* bhh2    = (const float*)d_in[12];
    const float* Wself2  = (const float*)d_in[13];
    const float* Wneigh2 = (const float*)d_in[14];
    const float* bneigh2 = (const float*)d_in[15];
    float* out = (float*)d_out;

    const int SM_COMB = (64 * 260 + 2 * F * 64) * 4;
    cudaFuncSetAttribute(combine_k, cudaFuncAttributeMaxDynamicSharedMemorySize, SM_COMB);

    int MT = (N_NODES + 63) / 64;   // 313

    // ---- layer 1 ----
    reorder3_k<<<64, 256>>>(Wih1, Whh1, bih1, bhh1);
    proj3_k<<<MT, 256>>>(x, 0);
    lstm3_k<<<MT, 256>>>(nbr);
    combprep_k<<<(2 * F * F + 255) / 256, 256>>>(Wself1, Wneigh1);
    combine_k<<<dim3(MT, 2), 256, SM_COMB>>>(x, bneigh1);

    // ---- layer 2 ----
    reorder3_k<<<64, 256>>>(Wih2, Whh2, bih2, bhh2);
    proj3_k<<<MT, 256>>>(nullptr, 1);
    lstm3_k<<<MT, 256>>>(nbr);
    final_k<<<(N_NODES * 32 + 255) / 256, 256>>>(Wself2, Wneigh2, bneigh2, out);
}

// round 8
// speedup vs baseline: 6.0163x; 1.3806x over previous
#include <cuda_runtime.h>
#include <cuda_fp16.h>

#define N_NODES 20000
#define DDEG 16
#define F 128
#define G4 512
#define LDH 136    // half-element row stride (272B: conflict-free ldmatrix)
#define TM 48      // lstm rows per CTA (3 m-tiles)
#define NMT 3

// -------- scratch (static device memory) --------
__device__ float g_XW[N_NODES * G4];      // input projection + bias (fp32), packed gate cols
__device__ float g_bias[G4];              // (bih+bhh), packed cols
__device__ uint2 g_BpIH[8 * 64 * 32];     // Wih fp16 B-fragments: [slice][tile][lane]
__device__ uint2 g_BpHH[8 * 64 * 32];     // Whh fp16 B-fragments
__device__ float g_HN[N_NODES * F];       // LSTM final hidden
__device__ float g_H1[N_NODES * F];       // layer-1 output (relu)
__device__ float g_WcT[2 * F * F];        // [Wself;Wneigh]^T

__device__ __forceinline__ float sigf(float x) {
    return __fdividef(1.0f, 1.0f + __expf(-x));
}
__device__ __forceinline__ float tanha(float x) {
    float y;
    asm("tanh.approx.f32 %0, %1;" : "=f"(y) : "f"(x));
    return y;
}
__device__ __forceinline__ float siga(float x) {
    return fmaf(tanha(0.5f * x), 0.5f, 0.5f);
}
__device__ __forceinline__ void ldmA(unsigned* a, const __half* p) {
    unsigned addr = (unsigned)__cvta_generic_to_shared(p);
    asm volatile("ldmatrix.sync.aligned.m8n8.x4.shared.b16 {%0,%1,%2,%3}, [%4];"
                 : "=r"(a[0]), "=r"(a[1]), "=r"(a[2]), "=r"(a[3]) : "r"(addr));
}
__device__ __forceinline__ void mma16(float* d, const unsigned* a, unsigned b0, unsigned b1) {
    asm volatile(
        "mma.sync.aligned.m16n8k16.row.col.f32.f16.f16.f32 "
        "{%0,%1,%2,%3}, {%4,%5,%6,%7}, {%8,%9}, {%0,%1,%2,%3};\n"
        : "+f"(d[0]), "+f"(d[1]), "+f"(d[2]), "+f"(d[3])
        : "r"(a[0]), "r"(a[1]), "r"(a[2]), "r"(a[3]), "r"(b0), "r"(b1));
}

// Packed gate-column mapping: col c <-> (hidden j, gate g):
//   j = 4*(c>>4) + ((c&7)>>1),  g = (c&1) + 2*((c>>3)&1)   (gate order i,f,g,o)

// ---- one-time weight packing: fp16 B fragments (m16n8k16) + packed bias
__global__ void reorder3_k(const float* __restrict__ Wih, const float* __restrict__ Whh,
                           const float* __restrict__ bih, const float* __restrict__ bhh) {
    int idx = blockIdx.x * blockDim.x + threadIdx.x;
    if (idx < 8 * 64 * 32) {
        int l = idx & 31, t = (idx >> 5) & 63, s = idx >> 11;
        int tig = l & 3, gid = l >> 2;
        int c = 8 * t + gid;
        int j = 4 * (c >> 4) + ((c & 7) >> 1);
        int g = (c & 1) + 2 * ((c >> 3) & 1);
        int row = g * F + j;
        int k0 = s * 16 + tig * 2;
        const float* wh = Whh + row * F + k0;
        const float* wi = Wih + row * F + k0;
        __half2 h0 = __floats2half2_rn(wh[0], wh[1]);
        __half2 h1 = __floats2half2_rn(wh[8], wh[9]);
        __half2 i0 = __floats2half2_rn(wi[0], wi[1]);
        __half2 i1 = __floats2half2_rn(wi[8], wi[9]);
        uint2 ph, pi;
        ph.x = *(unsigned*)&h0; ph.y = *(unsigned*)&h1;
        pi.x = *(unsigned*)&i0; pi.y = *(unsigned*)&i1;
        g_BpHH[idx] = ph;
        g_BpIH[idx] = pi;
    }
    if (idx < G4) {
        int c = idx;
        int j = 4 * (c >> 4) + ((c & 7) >> 1);
        int g = (c & 1) + 2 * ((c >> 3) & 1);
        g_bias[c] = bih[g * F + j] + bhh[g * F + j];
    }
}

// ---- tensor-core input projection: g_XW[m, c] = (A @ Wih^T)[m,c] + bias[c]
__global__ void __launch_bounds__(256, 1) proj3_k(const float* __restrict__ X, int from_h1) {
    __shared__ __half a_sh[64 * LDH];
    int tid = threadIdx.x, w = tid >> 5, lane = tid & 31;
    int gid = lane >> 2, tig = lane & 3;
    int m0 = blockIdx.x * 64;
    const float* Ap = from_h1 ? g_H1 : X;

    for (int i = tid; i < 64 * 16; i += 256) {
        int r = i >> 4, k8 = (i & 15) * 8;
        int m = m0 + r; if (m >= N_NODES) m = N_NODES - 1;
        float4 v0 = *(const float4*)(Ap + m * F + k8);
        float4 v1 = *(const float4*)(Ap + m * F + k8 + 4);
        __half2 p[4];
        p[0] = __floats2half2_rn(v0.x, v0.y);
        p[1] = __floats2half2_rn(v0.z, v0.w);
        p[2] = __floats2half2_rn(v1.x, v1.y);
        p[3] = __floats2half2_rn(v1.z, v1.w);
        *(uint4*)(a_sh + r * LDH + k8) = *(uint4*)p;
    }
    __syncthreads();

    float acc[4][8][4];
    #pragma unroll
    for (int a = 0; a < 4; ++a)
        #pragma unroll
        for (int b = 0; b < 8; ++b)
            #pragma unroll
            for (int cc = 0; cc < 4; ++cc) acc[a][b][cc] = 0.0f;

    uint2 bv[2][8];
    #pragma unroll
    for (int nt = 0; nt < 8; ++nt) bv[0][nt] = g_BpIH[(w * 8 + nt) * 32 + lane];

    int arow = lane & 15, acb = (lane >> 4) * 8;
    #pragma unroll
    for (int s = 0; s < 8; ++s) {
        int cur = s & 1;
        if (s < 7) {
            #pragma unroll
            for (int nt = 0; nt < 8; ++nt)
                bv[cur ^ 1][nt] = g_BpIH[((s + 1) * 64 + w * 8 + nt) * 32 + lane];
        }
        #pragma unroll
        for (int mt = 0; mt < 4; ++mt) {
            unsigned a[4];
            ldmA(a, a_sh + (mt * 16 + arow) * LDH + s * 16 + acb);
            #pragma unroll
            for (int nt = 0; nt < 8; ++nt)
                mma16(acc[mt][nt], a, bv[cur][nt].x, bv[cur][nt].y);
        }
    }

    #pragma unroll
    for (int nt = 0; nt < 8; ++nt) {
        int col = w * 64 + nt * 8 + 2 * tig;
        float2 b2 = *(const float2*)(g_bias + col);
        #pragma unroll
        for (int mt = 0; mt < 4; ++mt) {
            #pragma unroll
            for (int rr = 0; rr < 2; ++rr) {
                int m = m0 + mt * 16 + gid + rr * 8;
                if (m < N_NODES) {
                    float2 o;
                    o.x = acc[mt][nt][rr * 2 + 0] + b2.x;
                    o.y = acc[mt][nt][rr * 2 + 1] + b2.y;
                    *(float2*)(g_XW + m * G4 + col) = o;
                }
            }
        }
    }
}

// ---- fp16 tensor-core LSTM recurrence: 48 nodes/CTA (3 m-tiles), 16 steps,
//      double-buffered h, MUFU.TANH activations, cell state in registers.
__global__ void __launch_bounds__(256, 1) lstm4_k(const int* __restrict__ nbr) {
    __shared__ __half h_buf[2][TM * LDH];
    __shared__ int idx_sh[TM * DDEG];
    int tid = threadIdx.x, w = tid >> 5, lane = tid & 31;
    int gid = lane >> 2, tig = lane & 3;
    int m0 = blockIdx.x * TM;

    for (int i = tid; i < TM * LDH / 2; i += 256)
        ((__half2*)h_buf[0])[i] = __floats2half2_rn(0.f, 0.f);
    for (int i = tid; i < TM * DDEG; i += 256) {
        int r = i >> 4;
        int m = m0 + r; if (m >= N_NODES) m = N_NODES - 1;
        idx_sh[i] = nbr[m * DDEG + (i & 15)];
    }

    float cst[NMT][2][4];
    #pragma unroll
    for (int a = 0; a < NMT; ++a)
        #pragma unroll
        for (int b = 0; b < 2; ++b)
            #pragma unroll
            for (int cc = 0; cc < 4; ++cc) cst[a][b][cc] = 0.0f;

    __syncthreads();

    int arow = lane & 15, acb = (lane >> 4) * 8;
    int cur_buf = 0;

    for (int t = 0; t < DDEG; ++t) {
        const __half* cur = h_buf[cur_buf];
        __half* nxt = h_buf[cur_buf ^ 1];

        float acc[NMT][8][4];
        #pragma unroll
        for (int a = 0; a < NMT; ++a)
            #pragma unroll
            for (int b = 0; b < 8; ++b)
                #pragma unroll
                for (int cc = 0; cc < 4; ++cc) acc[a][b][cc] = 0.0f;

        uint2 bv[2][8];
        #pragma unroll
        for (int nt = 0; nt < 8; ++nt) bv[0][nt] = g_BpHH[(w * 8 + nt) * 32 + lane];

        #pragma unroll
        for (int s = 0; s < 8; ++s) {
            int c2 = s & 1;
            if (s < 7) {
                #pragma unroll
                for (int nt = 0; nt < 8; ++nt)
                    bv[c2 ^ 1][nt] = g_BpHH[((s + 1) * 64 + w * 8 + nt) * 32 + lane];
            }
            #pragma unroll
            for (int mt = 0; mt < NMT; ++mt) {
                unsigned a[4];
                ldmA(a, cur + (mt * 16 + arow) * LDH + s * 16 + acb);
                #pragma unroll
                for (int nt = 0; nt < 8; ++nt)
                    mma16(acc[mt][nt], a, bv[c2][nt].x, bv[c2][nt].y);
            }
        }

        // epilogue: thread owns gates (i,f)/(g,o) of unit j = 16w + 4*g16 + tig
        #pragma unroll
        for (int mt = 0; mt < NMT; ++mt) {
            #pragma unroll
            for (int rr = 0; rr < 2; ++rr) {
                int r = mt * 16 + gid + rr * 8;
                int nb = idx_sh[r * DDEG + t];
                const float* xwb = g_XW + nb * G4 + w * 64 + 2 * tig;
                #pragma unroll
                for (int g16 = 0; g16 < 4; ++g16) {
                    float2 xif = *(const float2*)(xwb + g16 * 16);
                    float2 xgo = *(const float2*)(xwb + g16 * 16 + 8);
                    float iv = acc[mt][2 * g16][rr * 2 + 0] + xif.x;
                    float fv = acc[mt][2 * g16][rr * 2 + 1] + xif.y;
                    float gv = acc[mt][2 * g16 + 1][rr * 2 + 0] + xgo.x;
                    float ov = acc[mt][2 * g16 + 1][rr * 2 + 1] + xgo.y;
                    float cn = siga(fv) * cst[mt][rr][g16] + siga(iv) * tanha(gv);
                    cst[mt][rr][g16] = cn;
                    nxt[r * LDH + w * 16 + 4 * g16 + tig] = __float2half_rn(siga(ov) * tanha(cn));
                }
            }
        }
        cur_buf ^= 1;
        __syncthreads();   // writes(t)->reads(t+1), and reads(t) done before writes(t+1)
    }

    const __half* hf = h_buf[cur_buf];
    for (int i = tid; i < TM * 16; i += 256) {
        int r = i >> 4, k8 = (i & 15) * 8;
        int m = m0 + r;
        if (m < N_NODES) {
            const __half2* src = (const __half2*)(hf + r * LDH + k8);
            float4 o0, o1;
            float2 t0 = __half22float2(src[0]), t1 = __half22float2(src[1]);
            float2 t2 = __half22float2(src[2]), t3 = __half22float2(src[3]);
            o0.x = t0.x; o0.y = t0.y; o0.z = t1.x; o0.w = t1.y;
            o1.x = t2.x; o1.y = t2.y; o1.z = t3.x; o1.w = t3.y;
            *(float4*)(g_HN + m * F + k8) = o0;
            *(float4*)(g_HN + m * F + k8 + 4) = o1;
        }
    }
}

// ---- pack [Wself;Wneigh] transposed
__global__ void combprep_k(const float* __restrict__ Wself, const float* __restrict__ Wneigh) {
    int idx = blockIdx.x * blockDim.x + threadIdx.x;
    if (idx < 2 * F * F) {
        int k = idx / F, col = idx % F;
        g_WcT[idx] = (k < F) ? Wself[col * F + k] : Wneigh[col * F + (k - F)];
    }
}

// ---- layer-1 combine: g_H1 = relu([x | HN] @ WcT + bneigh)
__global__ void __launch_bounds__(256) combine_k(const float* __restrict__ X,
                                                 const float* __restrict__ bn) {
    extern __shared__ float sm[];
    float* As = sm;                      // 64 x 260
    float* Ws = sm + 64 * 260;           // 256 x 64
    int m0 = blockIdx.x * 64;
    int co = blockIdx.y * 64;
    int tid = threadIdx.x;

    for (int i = tid; i < 64 * 64; i += 256) {
        int r = i >> 6, k4 = (i & 63) * 4;
        int m = m0 + r; if (m >= N_NODES) m = N_NODES - 1;
        float4 v = (k4 < F) ? *(const float4*)(X + m * F + k4)
                            : *(const float4*)(g_HN + m * F + (k4 - F));
        *(float4*)(As + r * 260 + k4) = v;
    }
    for (int i = tid; i < 2 * F * 16; i += 256) {
        int k = i >> 4, c4 = (i & 15) * 4;
        *(float4*)(Ws + k * 64 + c4) = *(const float4*)(g_WcT + k * F + co + c4);
    }
    __syncthreads();

    int ty = tid >> 4, tx = tid & 15;
    float acc[4][4] = {};
    #pragma unroll 8
    for (int k4 = 0; k4 < 64; ++k4) {
        float4 a[4], wv4[4];
        #pragma unroll
        for (int ri = 0; ri < 4; ++ri)
            a[ri] = *(const float4*)(As + (ty * 4 + ri) * 260 + k4 * 4);
        #pragma unroll
        for (int kk = 0; kk < 4; ++kk)
            wv4[kk] = *(const float4*)(Ws + (k4 * 4 + kk) * 64 + tx * 4);
        #pragma unroll
        for (int kk = 0; kk < 4; ++kk) {
            float4 wv = wv4[kk];
            #pragma unroll
            for (int ri = 0; ri < 4; ++ri) {
                float av = ((const float*)&a[ri])[kk];
                acc[ri][0] += av * wv.x;
                acc[ri][1] += av * wv.y;
                acc[ri][2] += av * wv.z;
                acc[ri][3] += av * wv.w;
            }
        }
    }
    #pragma unroll
    for (int ri = 0; ri < 4; ++ri) {
        int m = m0 + ty * 4 + ri;
        if (m < N_NODES) {
            float4 o;
            o.x = fmaxf(acc[ri][0] + bn[co + tx * 4 + 0], 0.0f);
            o.y = fmaxf(acc[ri][1] + bn[co + tx * 4 + 1], 0.0f);
            o.z = fmaxf(acc[ri][2] + bn[co + tx * 4 + 2], 0.0f);
            o.w = fmaxf(acc[ri][3] + bn[co + tx * 4 + 3], 0.0f);
            *(float4*)(g_H1 + m * F + co + tx * 4) = o;
        }
    }
}

// ---- final: out[n] = sigmoid(H1[n].Wself2 + HN[n].Wneigh2 + b)
__global__ void final_k(const float* __restrict__ Ws2, const float* __restrict__ Wn2,
                        const float* __restrict__ bn2, float* __restrict__ out) {
    int w = (blockIdx.x * blockDim.x + threadIdx.x) >> 5;
    int lane = threadIdx.x & 31;
    if (w >= N_NODES) return;
    float s = 0.0f;
    #pragma unroll
    for (int kk = 0; kk < 4; ++kk) {
        int k = lane + kk * 32;
        s += g_H1[w * F + k] * Ws2[k] + g_HN[w * F + k] * Wn2[k];
    }
    #pragma unroll
    for (int o = 16; o > 0; o >>= 1) s += __shfl_down_sync(0xffffffffu, s, o);
    if (lane == 0) out[w] = sigf(s + bn2[0]);
}

extern "C" void kernel_launch(void* const* d_in, const int* in_sizes, int n_in,
                              void* d_out, int out_size) {
    const float* x       = (const float*)d_in[0];
    const int*   nbr     = (const int*)d_in[1];
    const float* Wih1    = (const float*)d_in[2];
    const float* Whh1    = (const float*)d_in[3];
    const float* bih1    = (const float*)d_in[4];
    const float* bhh1    = (const float*)d_in[5];
    const float* Wself1  = (const float*)d_in[6];
    const float* Wneigh1 = (const float*)d_in[7];
    const float* bneigh1 = (const float*)d_in[8];
    const float* Wih2    = (const float*)d_in[9];
    const float* Whh2    = (const float*)d_in[10];
    const float* bih2    = (const float*)d_in[11];
    const float* bhh2    = (const float*)d_in[12];
    const float* Wself2  = (const float*)d_in[13];
    const float* Wneigh2 = (const float*)d_in[14];
    const float* bneigh2 = (const float*)d_in[15];
    float* out = (float*)d_out;

    const int SM_COMB = (64 * 260 + 2 * F * 64) * 4;
    cudaFuncSetAttribute(combine_k, cudaFuncAttributeMaxDynamicSharedMemorySize, SM_COMB);

    int MT64 = (N_NODES + 63) / 64;   // 313
    int MT48 = (N_NODES + TM - 1) / TM;  // 417

    // ---- layer 1 ----
    reorder3_k<<<64, 256>>>(Wih1, Whh1, bih1, bhh1);
    proj3_k<<<MT64, 256>>>(x, 0);
    lstm4_k<<<MT48, 256>>>(nbr);
    combprep_k<<<(2 * F * F + 255) / 256, 256>>>(Wself1, Wneigh1);
    combine_k<<<dim3(MT64, 2), 256, SM_COMB>>>(x, bneigh1);

    // ---- layer 2 ----
    reorder3_k<<<64, 256>>>(Wih2, Whh2, bih2, bhh2);
    proj3_k<<<MT64, 256>>>(nullptr, 1);
    lstm4_k<<<MT48, 256>>>(nbr);
    final_k<<<(N_NODES * 32 + 255) / 256, 256>>>(Wself2, Wneigh2, bneigh2, out);
}

// round 11
// speedup vs baseline: 6.7445x; 1.1210x over previous
#include <cuda_runtime.h>
#include <cuda_fp16.h>

#define N_NODES 20000
#define DDEG 16
#define F 128
#define G4 512
#define LDH 136    // half-element row stride (272B: conflict-free ldmatrix)
#define TM 48      // lstm rows per CTA (3 m-tiles)
#define NMT 3

// -------- scratch (static device memory) --------
__device__ float g_XW[N_NODES * G4];      // input projection + bias (fp32), packed gate cols
__device__ float g_bias[G4];              // (bih+bhh), packed cols
__device__ uint2 g_BpIH[8 * 64 * 32];     // Wih fp16 B-fragments: [slice][tile][lane]
__device__ uint2 g_BpHH[8 * 64 * 32];     // Whh fp16 B-fragments
__device__ float g_HN[N_NODES * F];       // LSTM final hidden
__device__ float g_H1[N_NODES * F];       // layer-1 output (relu)
__device__ float g_WcT[2 * F * F];        // [Wself;Wneigh]^T

__device__ __forceinline__ float sigf(float x) {
    return __fdividef(1.0f, 1.0f + __expf(-x));
}
__device__ __forceinline__ float tanha(float x) {
    float y;
    asm("tanh.approx.f32 %0, %1;" : "=f"(y) : "f"(x));
    return y;
}
__device__ __forceinline__ float siga(float x) {
    return fmaf(tanha(0.5f * x), 0.5f, 0.5f);
}
__device__ __forceinline__ void ldmA(unsigned* a, const __half* p) {
    unsigned addr = (unsigned)__cvta_generic_to_shared(p);
    asm volatile("ldmatrix.sync.aligned.m8n8.x4.shared.b16 {%0,%1,%2,%3}, [%4];"
                 : "=r"(a[0]), "=r"(a[1]), "=r"(a[2]), "=r"(a[3]) : "r"(addr));
}
__device__ __forceinline__ void mma16(float* d, const unsigned* a, unsigned b0, unsigned b1) {
    asm volatile(
        "mma.sync.aligned.m16n8k16.row.col.f32.f16.f16.f32 "
        "{%0,%1,%2,%3}, {%4,%5,%6,%7}, {%8,%9}, {%0,%1,%2,%3};\n"
        : "+f"(d[0]), "+f"(d[1]), "+f"(d[2]), "+f"(d[3])
        : "r"(a[0]), "r"(a[1]), "r"(a[2]), "r"(a[3]), "r"(b0), "r"(b1));
}

// Packed gate-column mapping: col c <-> (hidden j, gate g):
//   j = 4*(c>>4) + ((c&7)>>1),  g = (c&1) + 2*((c>>3)&1)   (gate order i,f,g,o)

// ---- one-time weight packing: fp16 B fragments (m16n8k16) + packed bias
__global__ void reorder3_k(const float* __restrict__ Wih, const float* __restrict__ Whh,
                           const float* __restrict__ bih, const float* __restrict__ bhh) {
    int idx = blockIdx.x * blockDim.x + threadIdx.x;
    if (idx < 8 * 64 * 32) {
        int l = idx & 31, t = (idx >> 5) & 63, s = idx >> 11;
        int tig = l & 3, gid = l >> 2;
        int c = 8 * t + gid;
        int j = 4 * (c >> 4) + ((c & 7) >> 1);
        int g = (c & 1) + 2 * ((c >> 3) & 1);
        int row = g * F + j;
        int k0 = s * 16 + tig * 2;
        const float* wh = Whh + row * F + k0;
        const float* wi = Wih + row * F + k0;
        __half2 h0 = __floats2half2_rn(wh[0], wh[1]);
        __half2 h1 = __floats2half2_rn(wh[8], wh[9]);
        __half2 i0 = __floats2half2_rn(wi[0], wi[1]);
        __half2 i1 = __floats2half2_rn(wi[8], wi[9]);
        uint2 ph, pi;
        ph.x = *(unsigned*)&h0; ph.y = *(unsigned*)&h1;
        pi.x = *(unsigned*)&i0; pi.y = *(unsigned*)&i1;
        g_BpHH[idx] = ph;
        g_BpIH[idx] = pi;
    }
    if (idx < G4) {
        int c = idx;
        int j = 4 * (c >> 4) + ((c & 7) >> 1);
        int g = (c & 1) + 2 * ((c >> 3) & 1);
        g_bias[c] = bih[g * F + j] + bhh[g * F + j];
    }
}

// ---- tensor-core input projection: g_XW[m, c] = (A @ Wih^T)[m,c] + bias[c]
__global__ void __launch_bounds__(256, 1) proj3_k(const float* __restrict__ X, int from_h1) {
    __shared__ __half a_sh[64 * LDH];
    int tid = threadIdx.x, w = tid >> 5, lane = tid & 31;
    int gid = lane >> 2, tig = lane & 3;
    int m0 = blockIdx.x * 64;
    const float* Ap = from_h1 ? g_H1 : X;

    for (int i = tid; i < 64 * 16; i += 256) {
        int r = i >> 4, k8 = (i & 15) * 8;
        int m = m0 + r; if (m >= N_NODES) m = N_NODES - 1;
        float4 v0 = *(const float4*)(Ap + m * F + k8);
        float4 v1 = *(const float4*)(Ap + m * F + k8 + 4);
        __half2 p[4];
        p[0] = __floats2half2_rn(v0.x, v0.y);
        p[1] = __floats2half2_rn(v0.z, v0.w);
        p[2] = __floats2half2_rn(v1.x, v1.y);
        p[3] = __floats2half2_rn(v1.z, v1.w);
        *(uint4*)(a_sh + r * LDH + k8) = *(uint4*)p;
    }
    __syncthreads();

    float acc[4][8][4];
    #pragma unroll
    for (int a = 0; a < 4; ++a)
        #pragma unroll
        for (int b = 0; b < 8; ++b)
            #pragma unroll
            for (int cc = 0; cc < 4; ++cc) acc[a][b][cc] = 0.0f;

    uint2 bv[2][8];
    #pragma unroll
    for (int nt = 0; nt < 8; ++nt) bv[0][nt] = g_BpIH[(w * 8 + nt) * 32 + lane];

    int arow = lane & 15, acb = (lane >> 4) * 8;
    #pragma unroll
    for (int s = 0; s < 8; ++s) {
        int cur = s & 1;
        if (s < 7) {
            #pragma unroll
            for (int nt = 0; nt < 8; ++nt)
                bv[cur ^ 1][nt] = g_BpIH[((s + 1) * 64 + w * 8 + nt) * 32 + lane];
        }
        #pragma unroll
        for (int mt = 0; mt < 4; ++mt) {
            unsigned a[4];
            ldmA(a, a_sh + (mt * 16 + arow) * LDH + s * 16 + acb);
            #pragma unroll
            for (int nt = 0; nt < 8; ++nt)
                mma16(acc[mt][nt], a, bv[cur][nt].x, bv[cur][nt].y);
        }
    }

    #pragma unroll
    for (int nt = 0; nt < 8; ++nt) {
        int col = w * 64 + nt * 8 + 2 * tig;
        float2 b2 = *(const float2*)(g_bias + col);
        #pragma unroll
        for (int mt = 0; mt < 4; ++mt) {
            #pragma unroll
            for (int rr = 0; rr < 2; ++rr) {
                int m = m0 + mt * 16 + gid + rr * 8;
                if (m < N_NODES) {
                    float2 o;
                    o.x = acc[mt][nt][rr * 2 + 0] + b2.x;
                    o.y = acc[mt][nt][rr * 2 + 1] + b2.y;
                    *(float2*)(g_XW + m * G4 + col) = o;
                }
            }
        }
    }
}

// ---- fp16 tensor-core LSTM recurrence: 48 nodes/CTA, 512 threads (16 warps),
//      each warp owns 32 gate-columns (4 n-tiles) -> 4 warps/SMSP so epilogue
//      MUFU overlaps other warps' HMMA. Double-buffered h, cell state in regs.
__global__ void __launch_bounds__(512, 1) lstm5_k(const int* __restrict__ nbr) {
    __shared__ __half h_buf[2][TM * LDH];
    __shared__ int idx_sh[TM * DDEG];
    int tid = threadIdx.x, w = tid >> 5, lane = tid & 31;
    int gid = lane >> 2, tig = lane & 3;
    int m0 = blockIdx.x * TM;

    for (int i = tid; i < TM * LDH / 2; i += 512)
        ((__half2*)h_buf[0])[i] = __floats2half2_rn(0.f, 0.f);
    for (int i = tid; i < TM * DDEG; i += 512) {
        int r = i >> 4;
        int m = m0 + r; if (m >= N_NODES) m = N_NODES - 1;
        idx_sh[i] = nbr[m * DDEG + (i & 15)];
    }

    float cst[NMT][2][2];
    #pragma unroll
    for (int a = 0; a < NMT; ++a)
        #pragma unroll
        for (int b = 0; b < 2; ++b)
            #pragma unroll
            for (int cc = 0; cc < 2; ++cc) cst[a][b][cc] = 0.0f;

    __syncthreads();

    int arow = lane & 15, acb = (lane >> 4) * 8;
    int cur_buf = 0;

    for (int t = 0; t < DDEG; ++t) {
        const __half* cur = h_buf[cur_buf];
        __half* nxt = h_buf[cur_buf ^ 1];

        float acc[NMT][4][4];
        #pragma unroll
        for (int a = 0; a < NMT; ++a)
            #pragma unroll
            for (int b = 0; b < 4; ++b)
                #pragma unroll
                for (int cc = 0; cc < 4; ++cc) acc[a][b][cc] = 0.0f;

        uint2 bv[2][4];
        #pragma unroll
        for (int nt = 0; nt < 4; ++nt) bv[0][nt] = g_BpHH[(w * 4 + nt) * 32 + lane];

        #pragma unroll
        for (int s = 0; s < 8; ++s) {
            int c2 = s & 1;
            if (s < 7) {
                #pragma unroll
                for (int nt = 0; nt < 4; ++nt)
                    bv[c2 ^ 1][nt] = g_BpHH[((s + 1) * 64 + w * 4 + nt) * 32 + lane];
            }
            #pragma unroll
            for (int mt = 0; mt < NMT; ++mt) {
                unsigned a[4];
                ldmA(a, cur + (mt * 16 + arow) * LDH + s * 16 + acb);
                #pragma unroll
                for (int nt = 0; nt < 4; ++nt)
                    mma16(acc[mt][nt], a, bv[c2][nt].x, bv[c2][nt].y);
            }
        }

        // epilogue: thread owns gates (i,f)/(g,o) of unit j = 8w + 4*g16 + tig, g16 in {0,1}
        #pragma unroll
        for (int mt = 0; mt < NMT; ++mt) {
            #pragma unroll
            for (int rr = 0; rr < 2; ++rr) {
                int r = mt * 16 + gid + rr * 8;
                int nb = idx_sh[r * DDEG + t];
                const float* xwb = g_XW + nb * G4 + w * 32 + 2 * tig;
                #pragma unroll
                for (int g16 = 0; g16 < 2; ++g16) {
                    float2 xif = *(const float2*)(xwb + g16 * 16);
                    float2 xgo = *(const float2*)(xwb + g16 * 16 + 8);
                    float iv = acc[mt][2 * g16][rr * 2 + 0] + xif.x;
                    float fv = acc[mt][2 * g16][rr * 2 + 1] + xif.y;
                    float gv = acc[mt][2 * g16 + 1][rr * 2 + 0] + xgo.x;
                    float ov = acc[mt][2 * g16 + 1][rr * 2 + 1] + xgo.y;
                    float cn = siga(fv) * cst[mt][rr][g16] + siga(iv) * tanha(gv);
                    cst[mt][rr][g16] = cn;
                    nxt[r * LDH + w * 8 + 4 * g16 + tig] = __float2half_rn(siga(ov) * tanha(cn));
                }
            }
        }
        cur_buf ^= 1;
        __syncthreads();   // writes(t)->reads(t+1), and reads(t) done before writes(t+1)
    }

    const __half* hf = h_buf[cur_buf];
    for (int i = tid; i < TM * 16; i += 512) {
        int r = i >> 4, k8 = (i & 15) * 8;
        int m = m0 + r;
        if (m < N_NODES) {
            const __half2* src = (const __half2*)(hf + r * LDH + k8);
            float4 o0, o1;
            float2 t0 = __half22float2(src[0]), t1 = __half22float2(src[1]);
            float2 t2 = __half22float2(src[2]), t3 = __half22float2(src[3]);
            o0.x = t0.x; o0.y = t0.y; o0.z = t1.x; o0.w = t1.y;
            o1.x = t2.x; o1.y = t2.y; o1.z = t3.x; o1.w = t3.y;
            *(float4*)(g_HN + m * F + k8) = o0;
            *(float4*)(g_HN + m * F + k8 + 4) = o1;
        }
    }
}

// ---- pack [Wself;Wneigh] transposed
__global__ void combprep_k(const float* __restrict__ Wself, const float* __restrict__ Wneigh) {
    int idx = blockIdx.x * blockDim.x + threadIdx.x;
    if (idx < 2 * F * F) {
        int k = idx / F, col = idx % F;
        g_WcT[idx] = (k < F) ? Wself[col * F + k] : Wneigh[col * F + (k - F)];
    }
}

// ---- layer-1 combine: g_H1 = relu([x | HN] @ WcT + bneigh)
__global__ void __launch_bounds__(256) combine_k(const float* __restrict__ X,
                                                 const float* __restrict__ bn) {
    extern __shared__ float sm[];
    float* As = sm;                      // 64 x 260
    float* Ws = sm + 64 * 260;           // 256 x 64
    int m0 = blockIdx.x * 64;
    int co = blockIdx.y * 64;
    int tid = threadIdx.x;

    for (int i = tid; i < 64 * 64; i += 256) {
        int r = i >> 6, k4 = (i & 63) * 4;
        int m = m0 + r; if (m >= N_NODES) m = N_NODES - 1;
        float4 v = (k4 < F) ? *(const float4*)(X + m * F + k4)
                            : *(const float4*)(g_HN + m * F + (k4 - F));
        *(float4*)(As + r * 260 + k4) = v;
    }
    for (int i = tid; i < 2 * F * 16; i += 256) {
        int k = i >> 4, c4 = (i & 15) * 4;
        *(float4*)(Ws + k * 64 + c4) = *(const float4*)(g_WcT + k * F + co + c4);
    }
    __syncthreads();

    int ty = tid >> 4, tx = tid & 15;
    float acc[4][4] = {};
    #pragma unroll 8
    for (int k4 = 0; k4 < 64; ++k4) {
        float4 a[4], wv4[4];
        #pragma unroll
        for (int ri = 0; ri < 4; ++ri)
            a[ri] = *(const float4*)(As + (ty * 4 + ri) * 260 + k4 * 4);
        #pragma unroll
        for (int kk = 0; kk < 4; ++kk)
            wv4[kk] = *(const float4*)(Ws + (k4 * 4 + kk) * 64 + tx * 4);
        #pragma unroll
        for (int kk = 0; kk < 4; ++kk) {
            float4 wv = wv4[kk];
            #pragma unroll
            for (int ri = 0; ri < 4; ++ri) {
                float av = ((const float*)&a[ri])[kk];
                acc[ri][0] += av * wv.x;
                acc[ri][1] += av * wv.y;
                acc[ri][2] += av * wv.z;
                acc[ri][3] += av * wv.w;
            }
        }
    }
    #pragma unroll
    for (int ri = 0; ri < 4; ++ri) {
        int m = m0 + ty * 4 + ri;
        if (m < N_NODES) {
            float4 o;
            o.x = fmaxf(acc[ri][0] + bn[co + tx * 4 + 0], 0.0f);
            o.y = fmaxf(acc[ri][1] + bn[co + tx * 4 + 1], 0.0f);
            o.z = fmaxf(acc[ri][2] + bn[co + tx * 4 + 2], 0.0f);
            o.w = fmaxf(acc[ri][3] + bn[co + tx * 4 + 3], 0.0f);
            *(float4*)(g_H1 + m * F + co + tx * 4) = o;
        }
    }
}

// ---- final: out[n] = sigmoid(H1[n].Wself2 + HN[n].Wneigh2 + b)
__global__ void final_k(const float* __restrict__ Ws2, const float* __restrict__ Wn2,
                        const float* __restrict__ bn2, float* __restrict__ out) {
    int w = (blockIdx.x * blockDim.x + threadIdx.x) >> 5;
    int lane = threadIdx.x & 31;
    if (w >= N_NODES) return;
    float s = 0.0f;
    #pragma unroll
    for (int kk = 0; kk < 4; ++kk) {
        int k = lane + kk * 32;
        s += g_H1[w * F + k] * Ws2[k] + g_HN[w * F + k] * Wn2[k];
    }
    #pragma unroll
    for (int o = 16; o > 0; o >>= 1) s += __shfl_down_sync(0xffffffffu, s, o);
    if (lane == 0) out[w] = sigf(s + bn2[0]);
}

extern "C" void kernel_launch(void* const* d_in, const int* in_sizes, int n_in,
                              void* d_out, int out_size) {
    const float* x       = (const float*)d_in[0];
    const int*   nbr     = (const int*)d_in[1];
    const float* Wih1    = (const float*)d_in[2];
    const float* Whh1    = (const float*)d_in[3];
    const float* bih1    = (const float*)d_in[4];
    const float* bhh1    = (const float*)d_in[5];
    const float* Wself1  = (const float*)d_in[6];
    const float* Wneigh1 = (const float*)d_in[7];
    const float* bneigh1 = (const float*)d_in[8];
    const float* Wih2    = (const float*)d_in[9];
    const float* Whh2    = (const float*)d_in[10];
    const float* bih2    = (const float*)d_in[11];
    const float* bhh2    = (const float*)d_in[12];
    const float* Wself2  = (const float*)d_in[13];
    const float* Wneigh2 = (const float*)d_in[14];
    const float* bneigh2 = (const float*)d_in[15];
    float* out = (float*)d_out;

    const int SM_COMB = (64 * 260 + 2 * F * 64) * 4;
    cudaFuncSetAttribute(combine_k, cudaFuncAttributeMaxDynamicSharedMemorySize, SM_COMB);

    int MT64 = (N_NODES + 63) / 64;       // 313
    int MT48 = (N_NODES + TM - 1) / TM;   // 417

    // ---- layer 1 ----
    reorder3_k<<<64, 256>>>(Wih1, Whh1, bih1, bhh1);
    proj3_k<<<MT64, 256>>>(x, 0);
    lstm5_k<<<MT48, 512>>>(nbr);
    combprep_k<<<(2 * F * F + 255) / 256, 256>>>(Wself1, Wneigh1);
    combine_k<<<dim3(MT64, 2), 256, SM_COMB>>>(x, bneigh1);

    // ---- layer 2 ----
    reorder3_k<<<64, 256>>>(Wih2, Whh2, bih2, bhh2);
    proj3_k<<<MT64, 256>>>(nullptr, 1);
    lstm5_k<<<MT48, 512>>>(nbr);
    final_k<<<(N_NODES * 32 + 255) / 256, 256>>>(Wself2, Wneigh2, bneigh2, out);
}

// round 12
// speedup vs baseline: 7.4610x; 1.1062x over previous
#include <cuda_runtime.h>
#include <cuda_fp16.h>

#define N_NODES 20000
#define DDEG 16
#define F 128
#define G4 512
#define LDH 136    // half-element row stride (272B: conflict-free ldmatrix)
#define TM 48      // lstm rows per CTA (3 m-tiles)
#define NMT 3

// -------- scratch (static device memory) --------
// XW packed fp16: for unit j = 8w+4b+c (w=0..15,b=0..1,c=0..3), storage pos p = 8w+2c+b,
// halves [p*4 .. p*4+3] = (i,f,g,o). Thread (w,tig=c) reads 8 halves at 32w+8c (16B aligned).
__device__ __half g_XWh[N_NODES * G4];
__device__ float g_bias[G4];              // (bih+bhh), packed gate cols
__device__ uint2 g_BpIH[8 * 64 * 32];     // Wih fp16 B-fragments: [slice][tile][lane]
__device__ uint2 g_BpHH[8 * 64 * 32];     // Whh fp16 B-fragments
__device__ float g_HN[N_NODES * F];       // LSTM final hidden
__device__ float g_H1[N_NODES * F];       // layer-1 output (relu)
__device__ float g_WcT[2 * F * F];        // [Wself;Wneigh]^T

__device__ __forceinline__ float sigf(float x) {
    return __fdividef(1.0f, 1.0f + __expf(-x));
}
__device__ __forceinline__ float tanha(float x) {
    float y;
    asm("tanh.approx.f32 %0, %1;" : "=f"(y) : "f"(x));
    return y;
}
__device__ __forceinline__ float siga(float x) {
    return fmaf(tanha(0.5f * x), 0.5f, 0.5f);
}
__device__ __forceinline__ void ldmA(unsigned* a, const __half* p) {
    unsigned addr = (unsigned)__cvta_generic_to_shared(p);
    asm volatile("ldmatrix.sync.aligned.m8n8.x4.shared.b16 {%0,%1,%2,%3}, [%4];"
                 : "=r"(a[0]), "=r"(a[1]), "=r"(a[2]), "=r"(a[3]) : "r"(addr));
}
__device__ __forceinline__ void mma16(float* d, const unsigned* a, unsigned b0, unsigned b1) {
    asm volatile(
        "mma.sync.aligned.m16n8k16.row.col.f32.f16.f16.f32 "
        "{%0,%1,%2,%3}, {%4,%5,%6,%7}, {%8,%9}, {%0,%1,%2,%3};\n"
        : "+f"(d[0]), "+f"(d[1]), "+f"(d[2]), "+f"(d[3])
        : "r"(a[0]), "r"(a[1]), "r"(a[2]), "r"(a[3]), "r"(b0), "r"(b1));
}

// Packed gate-column mapping (mma output space): col c <-> (hidden j, gate g):
//   j = 4*(c>>4) + ((c&7)>>1),  g = (c&1) + 2*((c>>3)&1)   (gate order i,f,g,o)

// ---- one-time weight packing: fp16 B fragments (m16n8k16) + packed bias
__global__ void reorder3_k(const float* __restrict__ Wih, const float* __restrict__ Whh,
                           const float* __restrict__ bih, const float* __restrict__ bhh) {
    int idx = blockIdx.x * blockDim.x + threadIdx.x;
    if (idx < 8 * 64 * 32) {
        int l = idx & 31, t = (idx >> 5) & 63, s = idx >> 11;
        int tig = l & 3, gid = l >> 2;
        int c = 8 * t + gid;
        int j = 4 * (c >> 4) + ((c & 7) >> 1);
        int g = (c & 1) + 2 * ((c >> 3) & 1);
        int row = g * F + j;
        int k0 = s * 16 + tig * 2;
        const float* wh = Whh + row * F + k0;
        const float* wi = Wih + row * F + k0;
        __half2 h0 = __floats2half2_rn(wh[0], wh[1]);
        __half2 h1 = __floats2half2_rn(wh[8], wh[9]);
        __half2 i0 = __floats2half2_rn(wi[0], wi[1]);
        __half2 i1 = __floats2half2_rn(wi[8], wi[9]);
        uint2 ph, pi;
        ph.x = *(unsigned*)&h0; ph.y = *(unsigned*)&h1;
        pi.x = *(unsigned*)&i0; pi.y = *(unsigned*)&i1;
        g_BpHH[idx] = ph;
        g_BpIH[idx] = pi;
    }
    if (idx < G4) {
        int c = idx;
        int j = 4 * (c >> 4) + ((c & 7) >> 1);
        int g = (c & 1) + 2 * ((c >> 3) & 1);
        g_bias[c] = bih[g * F + j] + bhh[g * F + j];
    }
}

// ---- tensor-core input projection -> packed fp16 XW (unit-major gate quads)
__global__ void __launch_bounds__(256, 1) proj4_k(const float* __restrict__ X, int from_h1) {
    extern __shared__ __half psm[];
    __half* a_sh = psm;                 // 64 * LDH
    __half* xw_sh = psm + 64 * LDH;     // 64 * 512 (final packed layout)
    int tid = threadIdx.x, w = tid >> 5, lane = tid & 31;
    int gid = lane >> 2, tig = lane & 3;
    int m0 = blockIdx.x * 64;
    const float* Ap = from_h1 ? g_H1 : X;

    for (int i = tid; i < 64 * 16; i += 256) {
        int r = i >> 4, k8 = (i & 15) * 8;
        int m = m0 + r; if (m >= N_NODES) m = N_NODES - 1;
        float4 v0 = *(const float4*)(Ap + m * F + k8);
        float4 v1 = *(const float4*)(Ap + m * F + k8 + 4);
        __half2 p[4];
        p[0] = __floats2half2_rn(v0.x, v0.y);
        p[1] = __floats2half2_rn(v0.z, v0.w);
        p[2] = __floats2half2_rn(v1.x, v1.y);
        p[3] = __floats2half2_rn(v1.z, v1.w);
        *(uint4*)(a_sh + r * LDH + k8) = *(uint4*)p;
    }
    __syncthreads();

    float acc[4][8][4];
    #pragma unroll
    for (int a = 0; a < 4; ++a)
        #pragma unroll
        for (int b = 0; b < 8; ++b)
            #pragma unroll
            for (int cc = 0; cc < 4; ++cc) acc[a][b][cc] = 0.0f;

    uint2 bv[2][8];
    #pragma unroll
    for (int nt = 0; nt < 8; ++nt) bv[0][nt] = g_BpIH[(w * 8 + nt) * 32 + lane];

    int arow = lane & 15, acb = (lane >> 4) * 8;
    #pragma unroll
    for (int s = 0; s < 8; ++s) {
        int cur = s & 1;
        if (s < 7) {
            #pragma unroll
            for (int nt = 0; nt < 8; ++nt)
                bv[cur ^ 1][nt] = g_BpIH[((s + 1) * 64 + w * 8 + nt) * 32 + lane];
        }
        #pragma unroll
        for (int mt = 0; mt < 4; ++mt) {
            unsigned a[4];
            ldmA(a, a_sh + (mt * 16 + arow) * LDH + s * 16 + acb);
            #pragma unroll
            for (int nt = 0; nt < 8; ++nt)
                mma16(acc[mt][nt], a, bv[cur][nt].x, bv[cur][nt].y);
        }
    }

    // stage into smem in final packed layout
    #pragma unroll
    for (int nt = 0; nt < 8; ++nt) {
        int c = w * 64 + nt * 8 + 2 * tig;
        int j = 4 * (c >> 4) + ((c & 7) >> 1);
        int g0 = 2 * ((c >> 3) & 1);                       // pair (c,c+1) = gates (g0, g0+1)
        int p = 8 * (j >> 3) + 2 * (j & 3) + ((j >> 2) & 1);
        float2 b2 = *(const float2*)(g_bias + c);
        #pragma unroll
        for (int mt = 0; mt < 4; ++mt) {
            #pragma unroll
            for (int rr = 0; rr < 2; ++rr) {
                int row = mt * 16 + gid + rr * 8;
                __half2 hv = __floats2half2_rn(acc[mt][nt][rr * 2 + 0] + b2.x,
                                               acc[mt][nt][rr * 2 + 1] + b2.y);
                *(__half2*)(xw_sh + row * G4 + p * 4 + g0) = hv;
            }
        }
    }
    __syncthreads();

    // coalesced writeout: 64 rows x 512 half
    for (int i = tid; i < 64 * 64; i += 256) {
        int r = i >> 6, ch = (i & 63) * 8;
        int m = m0 + r;
        if (m < N_NODES)
            *(uint4*)(g_XWh + m * G4 + ch) = *(const uint4*)(xw_sh + r * G4 + ch);
    }
}

// ---- fp16 tensor-core LSTM recurrence: 48 nodes/CTA, 512 threads (16 warps),
//      warp owns 32 gate-cols; XW gathered as 6 prefetched LDG.128/thread/step.
__global__ void __launch_bounds__(512, 1) lstm6_k(const int* __restrict__ nbr) {
    __shared__ __half h_buf[2][TM * LDH];
    __shared__ int idx_sh[TM * DDEG];
    int tid = threadIdx.x, w = tid >> 5, lane = tid & 31;
    int gid = lane >> 2, tig = lane & 3;
    int m0 = blockIdx.x * TM;

    for (int i = tid; i < TM * LDH / 2; i += 512)
        ((__half2*)h_buf[0])[i] = __floats2half2_rn(0.f, 0.f);
    for (int i = tid; i < TM * DDEG; i += 512) {
        int r = i >> 4;
        int m = m0 + r; if (m >= N_NODES) m = N_NODES - 1;
        idx_sh[i] = nbr[m * DDEG + (i & 15)];
    }

    float cst[NMT][2][2];
    #pragma unroll
    for (int a = 0; a < NMT; ++a)
        #pragma unroll
        for (int b = 0; b < 2; ++b)
            #pragma unroll
            for (int cc = 0; cc < 2; ++cc) cst[a][b][cc] = 0.0f;

    __syncthreads();

    int arow = lane & 15, acb = (lane >> 4) * 8;
    int xwoff = 32 * w + 8 * tig;   // half-index within node row (16B aligned)
    int cur_buf = 0;

    for (int t = 0; t < DDEG; ++t) {
        const __half* cur = h_buf[cur_buf];
        __half* nxt = h_buf[cur_buf ^ 1];

        // prefetch this step's XW quads (indices independent of h) — hides under mma
        uint4 xw4[NMT][2];
        #pragma unroll
        for (int mt = 0; mt < NMT; ++mt)
            #pragma unroll
            for (int rr = 0; rr < 2; ++rr) {
                int r = mt * 16 + gid + rr * 8;
                int nb = idx_sh[r * DDEG + t];
                xw4[mt][rr] = *(const uint4*)(g_XWh + nb * G4 + xwoff);
            }

        float acc[NMT][4][4];
        #pragma unroll
        for (int a = 0; a < NMT; ++a)
            #pragma unroll
            for (int b = 0; b < 4; ++b)
                #pragma unroll
                for (int cc = 0; cc < 4; ++cc) acc[a][b][cc] = 0.0f;

        uint2 bv[2][4];
        #pragma unroll
        for (int nt = 0; nt < 4; ++nt) bv[0][nt] = g_BpHH[(w * 4 + nt) * 32 + lane];

        #pragma unroll
        for (int s = 0; s < 8; ++s) {
            int c2 = s & 1;
            if (s < 7) {
                #pragma unroll
                for (int nt = 0; nt < 4; ++nt)
                    bv[c2 ^ 1][nt] = g_BpHH[((s + 1) * 64 + w * 4 + nt) * 32 + lane];
            }
            #pragma unroll
            for (int mt = 0; mt < NMT; ++mt) {
                unsigned a[4];
                ldmA(a, cur + (mt * 16 + arow) * LDH + s * 16 + acb);
                #pragma unroll
                for (int nt = 0; nt < 4; ++nt)
                    mma16(acc[mt][nt], a, bv[c2][nt].x, bv[c2][nt].y);
            }
        }

        // epilogue: thread owns units j = 8w + 4*g16 + tig, g16 in {0,1}
        #pragma unroll
        for (int mt = 0; mt < NMT; ++mt) {
            #pragma unroll
            for (int rr = 0; rr < 2; ++rr) {
                int r = mt * 16 + gid + rr * 8;
                const __half2* hp = (const __half2*)&xw4[mt][rr];
                #pragma unroll
                for (int g16 = 0; g16 < 2; ++g16) {
                    float2 xif = __half22float2(hp[2 * g16 + 0]);
                    float2 xgo = __half22float2(hp[2 * g16 + 1]);
                    float iv = acc[mt][2 * g16][rr * 2 + 0] + xif.x;
                    float fv = acc[mt][2 * g16][rr * 2 + 1] + xif.y;
                    float gv = acc[mt][2 * g16 + 1][rr * 2 + 0] + xgo.x;
                    float ov = acc[mt][2 * g16 + 1][rr * 2 + 1] + xgo.y;
                    float cn = siga(fv) * cst[mt][rr][g16] + siga(iv) * tanha(gv);
                    cst[mt][rr][g16] = cn;
                    nxt[r * LDH + w * 8 + 4 * g16 + tig] = __float2half_rn(siga(ov) * tanha(cn));
                }
            }
        }
        cur_buf ^= 1;
        __syncthreads();   // writes(t)->reads(t+1), and reads(t) done before writes(t+1)
    }

    const __half* hf = h_buf[cur_buf];
    for (int i = tid; i < TM * 16; i += 512) {
        int r = i >> 4, k8 = (i & 15) * 8;
        int m = m0 + r;
        if (m < N_NODES) {
            const __half2* src = (const __half2*)(hf + r * LDH + k8);
            float4 o0, o1;
            float2 t0 = __half22float2(src[0]), t1 = __half22float2(src[1]);
            float2 t2 = __half22float2(src[2]), t3 = __half22float2(src[3]);
            o0.x = t0.x; o0.y = t0.y; o0.z = t1.x; o0.w = t1.y;
            o1.x = t2.x; o1.y = t2.y; o1.z = t3.x; o1.w = t3.y;
            *(float4*)(g_HN + m * F + k8) = o0;
            *(float4*)(g_HN + m * F + k8 + 4) = o1;
        }
    }
}

// ---- pack [Wself;Wneigh] transposed
__global__ void combprep_k(const float* __restrict__ Wself, const float* __restrict__ Wneigh) {
    int idx = blockIdx.x * blockDim.x + threadIdx.x;
    if (idx < 2 * F * F) {
        int k = idx / F, col = idx % F;
        g_WcT[idx] = (k < F) ? Wself[col * F + k] : Wneigh[col * F + (k - F)];
    }
}

// ---- layer-1 combine: g_H1 = relu([x | HN] @ WcT + bneigh)
__global__ void __launch_bounds__(256) combine_k(const float* __restrict__ X,
                                                 const float* __restrict__ bn) {
    extern __shared__ float sm[];
    float* As = sm;                      // 64 x 260
    float* Ws = sm + 64 * 260;           // 256 x 64
    int m0 = blockIdx.x * 64;
    int co = blockIdx.y * 64;
    int tid = threadIdx.x;

    for (int i = tid; i < 64 * 64; i += 256) {
        int r = i >> 6, k4 = (i & 63) * 4;
        int m = m0 + r; if (m >= N_NODES) m = N_NODES - 1;
        float4 v = (k4 < F) ? *(const float4*)(X + m * F + k4)
                            : *(const float4*)(g_HN + m * F + (k4 - F));
        *(float4*)(As + r * 260 + k4) = v;
    }
    for (int i = tid; i < 2 * F * 16; i += 256) {
        int k = i >> 4, c4 = (i & 15) * 4;
        *(float4*)(Ws + k * 64 + c4) = *(const float4*)(g_WcT + k * F + co + c4);
    }
    __syncthreads();

    int ty = tid >> 4, tx = tid & 15;
    float acc[4][4] = {};
    #pragma unroll 8
    for (int k4 = 0; k4 < 64; ++k4) {
        float4 a[4], wv4[4];
        #pragma unroll
        for (int ri = 0; ri < 4; ++ri)
            a[ri] = *(const float4*)(As + (ty * 4 + ri) * 260 + k4 * 4);
        #pragma unroll
        for (int kk = 0; kk < 4; ++kk)
            wv4[kk] = *(const float4*)(Ws + (k4 * 4 + kk) * 64 + tx * 4);
        #pragma unroll
        for (int kk = 0; kk < 4; ++kk) {
            float4 wv = wv4[kk];
            #pragma unroll
            for (int ri = 0; ri < 4; ++ri) {
                float av = ((const float*)&a[ri])[kk];
                acc[ri][0] += av * wv.x;
                acc[ri][1] += av * wv.y;
                acc[ri][2] += av * wv.z;
                acc[ri][3] += av * wv.w;
            }
        }
    }
    #pragma unroll
    for (int ri = 0; ri < 4; ++ri) {
        int m = m0 + ty * 4 + ri;
        if (m < N_NODES) {
            float4 o;
            o.x = fmaxf(acc[ri][0] + bn[co + tx * 4 + 0], 0.0f);
            o.y = fmaxf(acc[ri][1] + bn[co + tx * 4 + 1], 0.0f);
            o.z = fmaxf(acc[ri][2] + bn[co + tx * 4 + 2], 0.0f);
            o.w = fmaxf(acc[ri][3] + bn[co + tx * 4 + 3], 0.0f);
            *(float4*)(g_H1 + m * F + co + tx * 4) = o;
        }
    }
}

// ---- final: out[n] = sigmoid(H1[n].Wself2 + HN[n].Wneigh2 + b)
__global__ void final_k(const float* __restrict__ Ws2, const float* __restrict__ Wn2,
                        const float* __restrict__ bn2, float* __restrict__ out) {
    int w = (blockIdx.x * blockDim.x + threadIdx.x) >> 5;
    int lane = threadIdx.x & 31;
    if (w >= N_NODES) return;
    float s = 0.0f;
    #pragma unroll
    for (int kk = 0; kk < 4; ++kk) {
        int k = lane + kk * 32;
        s += g_H1[w * F + k] * Ws2[k] + g_HN[w * F + k] * Wn2[k];
    }
    #pragma unroll
    for (int o = 16; o > 0; o >>= 1) s += __shfl_down_sync(0xffffffffu, s, o);
    if (lane == 0) out[w] = sigf(s + bn2[0]);
}

extern "C" void kernel_launch(void* const* d_in, const int* in_sizes, int n_in,
                              void* d_out, int out_size) {
    const float* x       = (const float*)d_in[0];
    const int*   nbr     = (const int*)d_in[1];
    const float* Wih1    = (const float*)d_in[2];
    const float* Whh1    = (const float*)d_in[3];
    const float* bih1    = (const float*)d_in[4];
    const float* bhh1    = (const float*)d_in[5];
    const float* Wself1  = (const float*)d_in[6];
    const float* Wneigh1 = (const float*)d_in[7];
    const float* bneigh1 = (const float*)d_in[8];
    const float* Wih2    = (const float*)d_in[9];
    const float* Whh2    = (const float*)d_in[10];
    const float* bih2    = (const float*)d_in[11];
    const float* bhh2    = (const float*)d_in[12];
    const float* Wself2  = (const float*)d_in[13];
    const float* Wneigh2 = (const float*)d_in[14];
    const float* bneigh2 = (const float*)d_in[15];
    float* out = (float*)d_out;

    const int SM_COMB = (64 * 260 + 2 * F * 64) * 4;
    const int SM_PROJ = (64 * LDH + 64 * G4) * 2;   // 82944 B
    cudaFuncSetAttribute(combine_k, cudaFuncAttributeMaxDynamicSharedMemorySize, SM_COMB);
    cudaFuncSetAttribute(proj4_k,   cudaFuncAttributeMaxDynamicSharedMemorySize, SM_PROJ);

    int MT64 = (N_NODES + 63) / 64;       // 313
    int MT48 = (N_NODES + TM - 1) / TM;   // 417

    // ---- layer 1 ----
    reorder3_k<<<64, 256>>>(Wih1, Whh1, bih1, bhh1);
    proj4_k<<<MT64, 256, SM_PROJ>>>(x, 0);
    lstm6_k<<<MT48, 512>>>(nbr);
    combprep_k<<<(2 * F * F + 255) / 256, 256>>>(Wself1, Wneigh1);
    combine_k<<<dim3(MT64, 2), 256, SM_COMB>>>(x, bneigh1);

    // ---- layer 2 ----
    reorder3_k<<<64, 256>>>(Wih2, Whh2, bih2, bhh2);
    proj4_k<<<MT64, 256, SM_PROJ>>>(nullptr, 1);
    lstm6_k<<<MT48, 512>>>(nbr);
    final_k<<<(N_NODES * 32 + 255) / 256, 256>>>(Wself2, Wneigh2, bneigh2, out);
}

// round 13
// speedup vs baseline: 7.4667x; 1.0008x over previous
#include <cuda_runtime.h>
#include <cuda_fp16.h>

#define N_NODES 20000
#define DDEG 16
#define F 128
#define G4 512
#define LDH 136    // half-element row stride (272B: conflict-free ldmatrix)
#define TM 48      // lstm rows per CTA (3 m-tiles)
#define NMT 3

// -------- scratch (static device memory) --------
// XW packed fp16: for unit j = 8w+4b+c (w=0..15,b=0..1,c=0..3), storage pos p = 8w+2c+b,
// halves [p*4 .. p*4+3] = (i,f,g,o). Thread (w,tig=c) reads 8 halves at 32w+8c (16B aligned).
__device__ __half g_XWh[N_NODES * G4];
__device__ float g_bias[G4];              // (bih+bhh), packed gate cols
__device__ uint2 g_BpIH[8 * 64 * 32];     // Wih fp16 B-fragments: [slice][tile][lane]
__device__ uint2 g_BpHH[8 * 64 * 32];     // Whh fp16 B-fragments
__device__ float g_HN[N_NODES * F];       // LSTM final hidden
__device__ float g_H1[N_NODES * F];       // layer-1 output (relu)
__device__ float g_WcT[2 * F * F];        // [Wself;Wneigh]^T

__device__ __forceinline__ float sigf(float x) {
    return __fdividef(1.0f, 1.0f + __expf(-x));
}
__device__ __forceinline__ float tanha(float x) {
    float y;
    asm("tanh.approx.f32 %0, %1;" : "=f"(y) : "f"(x));
    return y;
}
__device__ __forceinline__ float siga(float x) {
    return fmaf(tanha(0.5f * x), 0.5f, 0.5f);
}
__device__ __forceinline__ void ldmA(unsigned* a, const __half* p) {
    unsigned addr = (unsigned)__cvta_generic_to_shared(p);
    asm volatile("ldmatrix.sync.aligned.m8n8.x4.shared.b16 {%0,%1,%2,%3}, [%4];"
                 : "=r"(a[0]), "=r"(a[1]), "=r"(a[2]), "=r"(a[3]) : "r"(addr));
}
__device__ __forceinline__ void mma16(float* d, const unsigned* a, unsigned b0, unsigned b1) {
    asm volatile(
        "mma.sync.aligned.m16n8k16.row.col.f32.f16.f16.f32 "
        "{%0,%1,%2,%3}, {%4,%5,%6,%7}, {%8,%9}, {%0,%1,%2,%3};\n"
        : "+f"(d[0]), "+f"(d[1]), "+f"(d[2]), "+f"(d[3])
        : "r"(a[0]), "r"(a[1]), "r"(a[2]), "r"(a[3]), "r"(b0), "r"(b1));
}

// Packed gate-column mapping (mma output space): col c <-> (hidden j, gate g):
//   j = 4*(c>>4) + ((c&7)>>1),  g = (c&1) + 2*((c>>3)&1)   (gate order i,f,g,o)

// ---- one-time weight packing: fp16 B fragments (m16n8k16) + packed bias
__global__ void reorder3_k(const float* __restrict__ Wih, const float* __restrict__ Whh,
                           const float* __restrict__ bih, const float* __restrict__ bhh) {
    int idx = blockIdx.x * blockDim.x + threadIdx.x;
    if (idx < 8 * 64 * 32) {
        int l = idx & 31, t = (idx >> 5) & 63, s = idx >> 11;
        int tig = l & 3, gid = l >> 2;
        int c = 8 * t + gid;
        int j = 4 * (c >> 4) + ((c & 7) >> 1);
        int g = (c & 1) + 2 * ((c >> 3) & 1);
        int row = g * F + j;
        int k0 = s * 16 + tig * 2;
        const float* wh = Whh + row * F + k0;
        const float* wi = Wih + row * F + k0;
        __half2 h0 = __floats2half2_rn(wh[0], wh[1]);
        __half2 h1 = __floats2half2_rn(wh[8], wh[9]);
        __half2 i0 = __floats2half2_rn(wi[0], wi[1]);
        __half2 i1 = __floats2half2_rn(wi[8], wi[9]);
        uint2 ph, pi;
        ph.x = *(unsigned*)&h0; ph.y = *(unsigned*)&h1;
        pi.x = *(unsigned*)&i0; pi.y = *(unsigned*)&i1;
        g_BpHH[idx] = ph;
        g_BpIH[idx] = pi;
    }
    if (idx < G4) {
        int c = idx;
        int j = 4 * (c >> 4) + ((c & 7) >> 1);
        int g = (c & 1) + 2 * ((c >> 3) & 1);
        g_bias[c] = bih[g * F + j] + bhh[g * F + j];
    }
}

// ---- tensor-core input projection -> packed fp16 XW (unit-major gate quads)
__global__ void __launch_bounds__(256, 1) proj4_k(const float* __restrict__ X, int from_h1) {
    extern __shared__ __half psm[];
    __half* a_sh = psm;                 // 64 * LDH
    __half* xw_sh = psm + 64 * LDH;     // 64 * 512 (final packed layout)
    int tid = threadIdx.x, w = tid >> 5, lane = tid & 31;
    int gid = lane >> 2, tig = lane & 3;
    int m0 = blockIdx.x * 64;
    const float* Ap = from_h1 ? g_H1 : X;

    for (int i = tid; i < 64 * 16; i += 256) {
        int r = i >> 4, k8 = (i & 15) * 8;
        int m = m0 + r; if (m >= N_NODES) m = N_NODES - 1;
        float4 v0 = *(const float4*)(Ap + m * F + k8);
        float4 v1 = *(const float4*)(Ap + m * F + k8 + 4);
        __half2 p[4];
        p[0] = __floats2half2_rn(v0.x, v0.y);
        p[1] = __floats2half2_rn(v0.z, v0.w);
        p[2] = __floats2half2_rn(v1.x, v1.y);
        p[3] = __floats2half2_rn(v1.z, v1.w);
        *(uint4*)(a_sh + r * LDH + k8) = *(uint4*)p;
    }
    __syncthreads();

    float acc[4][8][4];
    #pragma unroll
    for (int a = 0; a < 4; ++a)
        #pragma unroll
        for (int b = 0; b < 8; ++b)
            #pragma unroll
            for (int cc = 0; cc < 4; ++cc) acc[a][b][cc] = 0.0f;

    uint2 bv[2][8];
    #pragma unroll
    for (int nt = 0; nt < 8; ++nt) bv[0][nt] = g_BpIH[(w * 8 + nt) * 32 + lane];

    int arow = lane & 15, acb = (lane >> 4) * 8;
    #pragma unroll
    for (int s = 0; s < 8; ++s) {
        int cur = s & 1;
        if (s < 7) {
            #pragma unroll
            for (int nt = 0; nt < 8; ++nt)
                bv[cur ^ 1][nt] = g_BpIH[((s + 1) * 64 + w * 8 + nt) * 32 + lane];
        }
        #pragma unroll
        for (int mt = 0; mt < 4; ++mt) {
            unsigned a[4];
            ldmA(a, a_sh + (mt * 16 + arow) * LDH + s * 16 + acb);
            #pragma unroll
            for (int nt = 0; nt < 8; ++nt)
                mma16(acc[mt][nt], a, bv[cur][nt].x, bv[cur][nt].y);
        }
    }

    // stage into smem in final packed layout
    #pragma unroll
    for (int nt = 0; nt < 8; ++nt) {
        int c = w * 64 + nt * 8 + 2 * tig;
        int j = 4 * (c >> 4) + ((c & 7) >> 1);
        int g0 = 2 * ((c >> 3) & 1);                       // pair (c,c+1) = gates (g0, g0+1)
        int p = 8 * (j >> 3) + 2 * (j & 3) + ((j >> 2) & 1);
        float2 b2 = *(const float2*)(g_bias + c);
        #pragma unroll
        for (int mt = 0; mt < 4; ++mt) {
            #pragma unroll
            for (int rr = 0; rr < 2; ++rr) {
                int row = mt * 16 + gid + rr * 8;
                __half2 hv = __floats2half2_rn(acc[mt][nt][rr * 2 + 0] + b2.x,
                                               acc[mt][nt][rr * 2 + 1] + b2.y);
                *(__half2*)(xw_sh + row * G4 + p * 4 + g0) = hv;
            }
        }
    }
    __syncthreads();

    // coalesced writeout: 64 rows x 512 half
    for (int i = tid; i < 64 * 64; i += 256) {
        int r = i >> 6, ch = (i & 63) * 8;
        int m = m0 + r;
        if (m < N_NODES)
            *(uint4*)(g_XWh + m * G4 + ch) = *(const uint4*)(xw_sh + r * G4 + ch);
    }
}

// ---- fp16 tensor-core LSTM recurrence: 48 nodes/CTA, 512 threads (16 warps),
//      warp owns 32 gate-cols; XW gathered as 6 prefetched LDG.128/thread/step.
__global__ void __launch_bounds__(512, 1) lstm6_k(const int* __restrict__ nbr) {
    __shared__ __half h_buf[2][TM * LDH];
    __shared__ int idx_sh[TM * DDEG];
    int tid = threadIdx.x, w = tid >> 5, lane = tid & 31;
    int gid = lane >> 2, tig = lane & 3;
    int m0 = blockIdx.x * TM;

    for (int i = tid; i < TM * LDH / 2; i += 512)
        ((__half2*)h_buf[0])[i] = __floats2half2_rn(0.f, 0.f);
    for (int i = tid; i < TM * DDEG; i += 512) {
        int r = i >> 4;
        int m = m0 + r; if (m >= N_NODES) m = N_NODES - 1;
        idx_sh[i] = nbr[m * DDEG + (i & 15)];
    }

    float cst[NMT][2][2];
    #pragma unroll
    for (int a = 0; a < NMT; ++a)
        #pragma unroll
        for (int b = 0; b < 2; ++b)
            #pragma unroll
            for (int cc = 0; cc < 2; ++cc) cst[a][b][cc] = 0.0f;

    __syncthreads();

    int arow = lane & 15, acb = (lane >> 4) * 8;
    int xwoff = 32 * w + 8 * tig;   // half-index within node row (16B aligned)
    int cur_buf = 0;

    for (int t = 0; t < DDEG; ++t) {
        const __half* cur = h_buf[cur_buf];
        __half* nxt = h_buf[cur_buf ^ 1];

        // prefetch this step's XW quads (indices independent of h) — hides under mma
        uint4 xw4[NMT][2];
        #pragma unroll
        for (int mt = 0; mt < NMT; ++mt)
            #pragma unroll
            for (int rr = 0; rr < 2; ++rr) {
                int r = mt * 16 + gid + rr * 8;
                int nb = idx_sh[r * DDEG + t];
                xw4[mt][rr] = *(const uint4*)(g_XWh + nb * G4 + xwoff);
            }

        float acc[NMT][4][4];
        #pragma unroll
        for (int a = 0; a < NMT; ++a)
            #pragma unroll
            for (int b = 0; b < 4; ++b)
                #pragma unroll
                for (int cc = 0; cc < 4; ++cc) acc[a][b][cc] = 0.0f;

        uint2 bv[2][4];
        #pragma unroll
        for (int nt = 0; nt < 4; ++nt) bv[0][nt] = g_BpHH[(w * 4 + nt) * 32 + lane];

        #pragma unroll
        for (int s = 0; s < 8; ++s) {
            int c2 = s & 1;
            if (s < 7) {
                #pragma unroll
                for (int nt = 0; nt < 4; ++nt)
                    bv[c2 ^ 1][nt] = g_BpHH[((s + 1) * 64 + w * 4 + nt) * 32 + lane];
            }
            #pragma unroll
            for (int mt = 0; mt < NMT; ++mt) {
                unsigned a[4];
                ldmA(a, cur + (mt * 16 + arow) * LDH + s * 16 + acb);
                #pragma unroll
                for (int nt = 0; nt < 4; ++nt)
                    mma16(acc[mt][nt], a, bv[c2][nt].x, bv[c2][nt].y);
            }
        }

        // epilogue: thread owns units j = 8w + 4*g16 + tig, g16 in {0,1}
        #pragma unroll
        for (int mt = 0; mt < NMT; ++mt) {
            #pragma unroll
            for (int rr = 0; rr < 2; ++rr) {
                int r = mt * 16 + gid + rr * 8;
                const __half2* hp = (const __half2*)&xw4[mt][rr];
                #pragma unroll
                for (int g16 = 0; g16 < 2; ++g16) {
                    float2 xif = __half22float2(hp[2 * g16 + 0]);
                    float2 xgo = __half22float2(hp[2 * g16 + 1]);
                    float iv = acc[mt][2 * g16][rr * 2 + 0] + xif.x;
                    float fv = acc[mt][2 * g16][rr * 2 + 1] + xif.y;
                    float gv = acc[mt][2 * g16 + 1][rr * 2 + 0] + xgo.x;
                    float ov = acc[mt][2 * g16 + 1][rr * 2 + 1] + xgo.y;
                    float cn = siga(fv) * cst[mt][rr][g16] + siga(iv) * tanha(gv);
                    cst[mt][rr][g16] = cn;
                    nxt[r * LDH + w * 8 + 4 * g16 + tig] = __float2half_rn(siga(ov) * tanha(cn));
                }
            }
        }
        cur_buf ^= 1;
        __syncthreads();   // writes(t)->reads(t+1), and reads(t) done before writes(t+1)
    }

    const __half* hf = h_buf[cur_buf];
    for (int i = tid; i < TM * 16; i += 512) {
        int r = i >> 4, k8 = (i & 15) * 8;
        int m = m0 + r;
        if (m < N_NODES) {
            const __half2* src = (const __half2*)(hf + r * LDH + k8);
            float4 o0, o1;
            float2 t0 = __half22float2(src[0]), t1 = __half22float2(src[1]);
            float2 t2 = __half22float2(src[2]), t3 = __half22float2(src[3]);
            o0.x = t0.x; o0.y = t0.y; o0.z = t1.x; o0.w = t1.y;
            o1.x = t2.x; o1.y = t2.y; o1.z = t3.x; o1.w = t3.y;
            *(float4*)(g_HN + m * F + k8) = o0;
            *(float4*)(g_HN + m * F + k8 + 4) = o1;
        }
    }
}

// ---- pack [Wself;Wneigh] transposed
__global__ void combprep_k(const float* __restrict__ Wself, const float* __restrict__ Wneigh) {
    int idx = blockIdx.x * blockDim.x + threadIdx.x;
    if (idx < 2 * F * F) {
        int k = idx / F, col = idx % F;
        g_WcT[idx] = (k < F) ? Wself[col * F + k] : Wneigh[col * F + (k - F)];
    }
}

// ---- layer-1 combine: g_H1 = relu([x | HN] @ WcT + bneigh)
__global__ void __launch_bounds__(256) combine_k(const float* __restrict__ X,
                                                 const float* __restrict__ bn) {
    extern __shared__ float sm[];
    float* As = sm;                      // 64 x 260
    float* Ws = sm + 64 * 260;           // 256 x 64
    int m0 = blockIdx.x * 64;
    int co = blockIdx.y * 64;
    int tid = threadIdx.x;

    for (int i = tid; i < 64 * 64; i += 256) {
        int r = i >> 6, k4 = (i & 63) * 4;
        int m = m0 + r; if (m >= N_NODES) m = N_NODES - 1;
        float4 v = (k4 < F) ? *(const float4*)(X + m * F + k4)
                            : *(const float4*)(g_HN + m * F + (k4 - F));
        *(float4*)(As + r * 260 + k4) = v;
    }
    for (int i = tid; i < 2 * F * 16; i += 256) {
        int k = i >> 4, c4 = (i & 15) * 4;
        *(float4*)(Ws + k * 64 + c4) = *(const float4*)(g_WcT + k * F + co + c4);
    }
    __syncthreads();

    int ty = tid >> 4, tx = tid & 15;
    float acc[4][4] = {};
    #pragma unroll 8
    for (int k4 = 0; k4 < 64; ++k4) {
        float4 a[4], wv4[4];
        #pragma unroll
        for (int ri = 0; ri < 4; ++ri)
            a[ri] = *(const float4*)(As + (ty * 4 + ri) * 260 + k4 * 4);
        #pragma unroll
        for (int kk = 0; kk < 4; ++kk)
            wv4[kk] = *(const float4*)(Ws + (k4 * 4 + kk) * 64 + tx * 4);
        #pragma unroll
        for (int kk = 0; kk < 4; ++kk) {
            float4 wv = wv4[kk];
            #pragma unroll
            for (int ri = 0; ri < 4; ++ri) {
                float av = ((const float*)&a[ri])[kk];
                acc[ri][0] += av * wv.x;
                acc[ri][1] += av * wv.y;
                acc[ri][2] += av * wv.z;
                acc[ri][3] += av * wv.w;
            }
        }
    }
    #pragma unroll
    for (int ri = 0; ri < 4; ++ri) {
        int m = m0 + ty * 4 + ri;
        if (m < N_NODES) {
            float4 o;
            o.x = fmaxf(acc[ri][0] + bn[co + tx * 4 + 0], 0.0f);
            o.y = fmaxf(acc[ri][1] + bn[co + tx * 4 + 1], 0.0f);
            o.z = fmaxf(acc[ri][2] + bn[co + tx * 4 + 2], 0.0f);
            o.w = fmaxf(acc[ri][3] + bn[co + tx * 4 + 3], 0.0f);
            *(float4*)(g_H1 + m * F + co + tx * 4) = o;
        }
    }
}

// ---- final: out[n] = sigmoid(H1[n].Wself2 + HN[n].Wneigh2 + b)
__global__ void final_k(const float* __restrict__ Ws2, const float* __restrict__ Wn2,
                        const float* __restrict__ bn2, float* __restrict__ out) {
    int w = (blockIdx.x * blockDim.x + threadIdx.x) >> 5;
    int lane = threadIdx.x & 31;
    if (w >= N_NODES) return;
    float s = 0.0f;
    #pragma unroll
    for (int kk = 0; kk < 4; ++kk) {
        int k = lane + kk * 32;
        s += g_H1[w * F + k] * Ws2[k] + g_HN[w * F + k] * Wn2[k];
    }
    #pragma unroll
    for (int o = 16; o > 0; o >>= 1) s += __shfl_down_sync(0xffffffffu, s, o);
    if (lane == 0) out[w] = sigf(s + bn2[0]);
}

extern "C" void kernel_launch(void* const* d_in, const int* in_sizes, int n_in,
                              void* d_out, int out_size) {
    const float* x       = (const float*)d_in[0];
    const int*   nbr     = (const int*)d_in[1];
    const float* Wih1    = (const float*)d_in[2];
    const float* Whh1    = (const float*)d_in[3];
    const float* bih1    = (const float*)d_in[4];
    const float* bhh1    = (const float*)d_in[5];
    const float* Wself1  = (const float*)d_in[6];
    const float* Wneigh1 = (const float*)d_in[7];
    const float* bneigh1 = (const float*)d_in[8];
    const float* Wih2    = (const float*)d_in[9];
    const float* Whh2    = (const float*)d_in[10];
    const float* bih2    = (const float*)d_in[11];
    const float* bhh2    = (const float*)d_in[12];
    const float* Wself2  = (const float*)d_in[13];
    const float* Wneigh2 = (const float*)d_in[14];
    const float* bneigh2 = (const float*)d_in[15];
    float* out = (float*)d_out;

    const int SM_COMB = (64 * 260 + 2 * F * 64) * 4;
    const int SM_PROJ = (64 * LDH + 64 * G4) * 2;   // 82944 B
    cudaFuncSetAttribute(combine_k, cudaFuncAttributeMaxDynamicSharedMemorySize, SM_COMB);
    cudaFuncSetAttribute(proj4_k,   cudaFuncAttributeMaxDynamicSharedMemorySize, SM_PROJ);

    int MT64 = (N_NODES + 63) / 64;       // 313
    int MT48 = (N_NODES + TM - 1) / TM;   // 417

    // ---- layer 1 ----
    reorder3_k<<<64, 256>>>(Wih1, Whh1, bih1, bhh1);
    proj4_k<<<MT64, 256, SM_PROJ>>>(x, 0);
    lstm6_k<<<MT48, 512>>>(nbr);
    combprep_k<<<(2 * F * F + 255) / 256, 256>>>(Wself1, Wneigh1);
    combine_k<<<dim3(MT64, 2), 256, SM_COMB>>>(x, bneigh1);

    // ---- layer 2 ----
    reorder3_k<<<64, 256>>>(Wih2, Whh2, bih2, bhh2);
    proj4_k<<<MT64, 256, SM_PROJ>>>(nullptr, 1);
    lstm6_k<<<MT48, 512>>>(nbr);
    final_k<<<(N_NODES * 32 + 255) / 256, 256>>>(Wself2, Wneigh2, bneigh2, out);
}